// round 14
// baseline (speedup 1.0000x reference)
#include <cuda_runtime.h>
#include <math.h>

#define D   128
#define B   128
#define S   200
#define NQ  10000
#define NC  500

// ---------------- scratch tables (device globals; no allocation) ----------------
__device__ float g_M1[D*D];      // W_fuse_top @ W_absorb_top
__device__ float g_M2[D*D];      // W_fuse_top @ W_forget_bot
__device__ float g_UT[100*D];    // embed_use_time @ W_absorb_mid
__device__ float g_HA[12*D];     // embed_hint_attempt @ W_absorb_bot
__device__ float g_IT[100*D];    // embed_interval_time @ W_forget_mid
__device__ float g_s1[D];        // colsum(W_fuse_bot)
__device__ float g_v1[D];        // s1 @ W_absorb_top
__device__ float g_v2[D];        // s1 @ W_forget_bot
__device__ float g_bA[D];        // b_fuse @ W_absorb_top + b_absorb
__device__ float g_bF[D];        // b_fuse @ W_forget_bot + b_forget
__device__ float g_P1[NQ*D];     // embed_question @ M1
__device__ float g_P2[NQ*D];     // embed_question @ M2
__device__ float g_qd[NQ];       // 10*sigmoid(disc)
__device__ float g_qdm[NQ];      // sum_k qdiff_k * mask_k  (per question)
__device__ float g_rnC[NC];      // 1/max(|concept|,eps)

// packed f32x2 ops (sm_100+)
__device__ __forceinline__ void ffma2(unsigned long long &d,
                                      unsigned long long a, unsigned long long b){
    asm("fma.rn.f32x2 %0, %1, %2, %0;" : "+l"(d) : "l"(a), "l"(b));
}
__device__ __forceinline__ void fadd2(unsigned long long &d, unsigned long long a){
    asm("add.rn.f32x2 %0, %0, %1;" : "+l"(d) : "l"(a));
}
__device__ __forceinline__ float ulo(unsigned long long v){ return __uint_as_float((unsigned)v); }
__device__ __forceinline__ float uhi(unsigned long long v){ return __uint_as_float((unsigned)(v>>32)); }
__device__ __forceinline__ unsigned long long dup2(float m){
    unsigned long long r; unsigned mb = __float_as_uint(m);
    asm("mov.b64 %0, {%1, %1};" : "=l"(r) : "r"(mb));
    return r;
}

// probe: keeps the ncu -s window landing on the scan kernel
__global__ void probe_kernel(){}

// ---------------- prepA: small composite mats + tables ----------------
__global__ void __launch_bounds__(128) prepA_kernel(
    const float* __restrict__ Wfuse, const float* __restrict__ bfuse,
    const float* __restrict__ Wabs,  const float* __restrict__ babs,
    const float* __restrict__ Wfor,  const float* __restrict__ bfor,
    const float* __restrict__ EQd,   const float* __restrict__ EC,
    const float* __restrict__ EIT,   const float* __restrict__ EUT,
    const float* __restrict__ EHA)
{
    __shared__ float sh[D];
    const int tid = threadIdx.x;
    const int bid = blockIdx.x;

    if (bid < 468) {
        const float* vrow; const float* Wb; float* outp;
        if (bid < 128)      { vrow = Wfuse + bid*D;        Wb = Wabs;           outp = g_M1 + bid*D; }
        else if (bid < 256) { vrow = Wfuse + (bid-128)*D;  Wb = Wfor + 2*D*D;   outp = g_M2 + (bid-128)*D; }
        else if (bid < 356) { vrow = EUT + (bid-256)*D;    Wb = Wabs + D*D;     outp = g_UT + (bid-256)*D; }
        else if (bid < 368) { vrow = EHA + (bid-356)*D;    Wb = Wabs + 2*D*D;   outp = g_HA + (bid-356)*D; }
        else                { vrow = EIT + (bid-368)*D;    Wb = Wfor + D*D;     outp = g_IT + (bid-368)*D; }
        sh[tid] = vrow[tid];
        __syncthreads();
        float a0=0.f,a1=0.f,a2=0.f,a3=0.f,a4=0.f,a5=0.f,a6=0.f,a7=0.f;
        #pragma unroll
        for (int jj=0; jj<D; jj+=8){
            a0 += sh[jj+0]*Wb[(jj+0)*D+tid];
            a1 += sh[jj+1]*Wb[(jj+1)*D+tid];
            a2 += sh[jj+2]*Wb[(jj+2)*D+tid];
            a3 += sh[jj+3]*Wb[(jj+3)*D+tid];
            a4 += sh[jj+4]*Wb[(jj+4)*D+tid];
            a5 += sh[jj+5]*Wb[(jj+5)*D+tid];
            a6 += sh[jj+6]*Wb[(jj+6)*D+tid];
            a7 += sh[jj+7]*Wb[(jj+7)*D+tid];
        }
        outp[tid] = ((a0+a1)+(a2+a3))+((a4+a5)+(a6+a7));
    } else if (bid == 468) {
        float a0=0.f,a1=0.f,a2=0.f,a3=0.f;
        #pragma unroll
        for (int k=0;k<D;k+=4){
            a0 += Wfuse[(D+k+0)*D+tid]; a1 += Wfuse[(D+k+1)*D+tid];
            a2 += Wfuse[(D+k+2)*D+tid]; a3 += Wfuse[(D+k+3)*D+tid];
        }
        g_s1[tid]=(a0+a1)+(a2+a3);
    } else if (bid == 469) {
        sh[tid]=bfuse[tid]; __syncthreads();
        float a0=0.f,a1=0.f,a2=0.f,a3=0.f;
        #pragma unroll
        for (int k=0;k<D;k+=4){
            a0 += sh[k+0]*Wabs[(k+0)*D+tid]; a1 += sh[k+1]*Wabs[(k+1)*D+tid];
            a2 += sh[k+2]*Wabs[(k+2)*D+tid]; a3 += sh[k+3]*Wabs[(k+3)*D+tid];
        }
        g_bA[tid] = (a0+a1)+(a2+a3) + babs[tid];
    } else if (bid == 470) {
        sh[tid]=bfuse[tid]; __syncthreads();
        float a0=0.f,a1=0.f,a2=0.f,a3=0.f;
        #pragma unroll
        for (int k=0;k<D;k+=4){
            a0 += sh[k+0]*Wfor[(2*D+k+0)*D+tid]; a1 += sh[k+1]*Wfor[(2*D+k+1)*D+tid];
            a2 += sh[k+2]*Wfor[(2*D+k+2)*D+tid]; a3 += sh[k+3]*Wfor[(2*D+k+3)*D+tid];
        }
        g_bF[tid] = (a0+a1)+(a2+a3) + bfor[tid];
    } else if (bid < 475) {
        int c = (bid-471)*128 + tid;
        if (c < NC){
            float s=0.f;
            #pragma unroll
            for (int dd=0; dd<D; dd+=4){
                float4 e = *(const float4*)&EC[c*D+dd];
                s += e.x*e.x + e.y*e.y + e.z*e.z + e.w*e.w;
            }
            g_rnC[c] = 1.f/fmaxf(sqrtf(s), 1e-8f);
        }
    } else {
        int q = (bid-475)*128 + tid;
        if (q < NQ) g_qd[q] = 10.f/(1.f+__expf(-EQd[q]));
    }
}

// ---------------- prepB: 8-question tiles, f32x2-packed, balanced qdm ----------------
#define NBQ 139
#define QPB 72
#define SMEM_B ((2*D*D + 8*D) * (int)sizeof(float))

__global__ void __launch_bounds__(256) prepB_kernel(
    const float* __restrict__ EQ, const float* __restrict__ EC,
    const int* __restrict__ q2c, const int* __restrict__ q2cm,
    const float* __restrict__ Wabs, const float* __restrict__ Wfor)
{
    const int tid = threadIdx.x;
    const int bid = blockIdx.x;

    if (bid >= NBQ){                       // v1 / v2 blocks (need g_s1 from prepA)
        __shared__ float s1s[D];
        if (tid < D) s1s[tid] = g_s1[tid];
        __syncthreads();
        if (tid < D){
            const float* Wb = (bid==NBQ) ? Wabs : (Wfor + 2*D*D);
            float a0=0.f,a1=0.f,a2=0.f,a3=0.f;
            #pragma unroll
            for (int jj=0;jj<D;jj+=4){
                a0 += s1s[jj+0]*Wb[(jj+0)*D+tid]; a1 += s1s[jj+1]*Wb[(jj+1)*D+tid];
                a2 += s1s[jj+2]*Wb[(jj+2)*D+tid]; a3 += s1s[jj+3]*Wb[(jj+3)*D+tid];
            }
            float a = (a0+a1)+(a2+a3);
            if (bid==NBQ) g_v1[tid]=a; else g_v2[tid]=a;
        }
        return;
    }

    extern __shared__ float smem[];
    float* M1s = smem;            // D*D
    float* M2s = smem + D*D;      // D*D
    float* E8  = smem + 2*D*D;    // 8 questions interleaved: E8[jj*8+q]

    const int w    = tid>>5;      // warp 0..7 — qdm question slot
    const int lane = tid&31;
    const int eq   = tid&7;       // E-staging question slot
    const int eg   = tid>>3;      // E-staging jj group (0..31)

    for (int i=tid; i<D*D; i+=256){ M1s[i]=g_M1[i]; M2s[i]=g_M2[i]; }

    const int qbase = bid*QPB;

    float4 eR = make_float4(0.f,0.f,0.f,0.f);
    { int q = qbase+eq; if (q<NQ) eR = *(const float4*)&EQ[q*D + eg*4]; }
    int4 cidN = make_int4(0,0,0,0);
    float rn0N=0,rn1N=0,rn2N=0,rn3N=0,m0N=0,m1N=0,m2N=0,m3N=0;
    { int q = qbase+w;
      if (q<NQ){
        cidN = ((const int4*)q2c)[q];
        rn0N=g_rnC[cidN.x]; rn1N=g_rnC[cidN.y]; rn2N=g_rnC[cidN.z]; rn3N=g_rnC[cidN.w];
        int4 mm = ((const int4*)q2cm)[q];
        m0N=(float)mm.x; m1N=(float)mm.y; m2N=(float)mm.z; m3N=(float)mm.w;
      }
    }
    __syncthreads();   // M1s/M2s visible

    for (int tt=0; tt<9; tt++){
        const int qb = qbase + tt*8;
        {
            int jb = eg*4;
            E8[(jb+0)*8+eq]=eR.x; E8[(jb+1)*8+eq]=eR.y;
            E8[(jb+2)*8+eq]=eR.z; E8[(jb+3)*8+eq]=eR.w;
        }
        const int4  cidC = cidN;
        const float rn0C=rn0N, rn1C=rn1N, rn2C=rn2N, rn3C=rn3N;
        const float m0C=m0N, m1C=m1N, m2C=m2N, m3C=m3N;
        __syncthreads();

        if (tt<8){
            int q = qb+8+eq;
            eR = make_float4(0.f,0.f,0.f,0.f);
            if (q<NQ) eR = *(const float4*)&EQ[q*D + eg*4];
            int qm = qb+8+w;
            if (qm<NQ){
                cidN = ((const int4*)q2c)[qm];
                rn0N=g_rnC[cidN.x]; rn1N=g_rnC[cidN.y]; rn2N=g_rnC[cidN.z]; rn3N=g_rnC[cidN.w];
                int4 mm = ((const int4*)q2cm)[qm];
                m0N=(float)mm.x; m1N=(float)mm.y; m2N=(float)mm.z; m3N=(float)mm.w;
            }
        }

        const float* ec0 = EC + cidC.x*D + lane;
        const float* ec1 = EC + cidC.y*D + lane;
        const float* ec2 = EC + cidC.z*D + lane;
        const float* ec3 = EC + cidC.w*D + lane;
        float x00=ec0[0], x01=ec0[32], x02=ec0[64], x03=ec0[96];
        float x10=ec1[0], x11=ec1[32], x12=ec1[64], x13=ec1[96];
        float x20=ec2[0], x21=ec2[32], x22=ec2[64], x23=ec2[96];
        float x30=ec3[0], x31=ec3[32], x32=ec3[64], x33=ec3[96];

        {
            const int halfp = tid>>7, jj = tid&127;
            const float* Ms = halfp ? M2s : M1s;
            unsigned long long A0=0ull,A1=0ull,A2=0ull,A3=0ull;
            const ulonglong2* Ev = (const ulonglong2*)E8;
            #pragma unroll 8
            for (int jk=0; jk<D; jk++){
                ulonglong2 u0 = Ev[jk*2];
                ulonglong2 u1 = Ev[jk*2+1];
                unsigned long long mm = dup2(Ms[jk*D+jj]);
                ffma2(A0, u0.x, mm);
                ffma2(A1, u0.y, mm);
                ffma2(A2, u1.x, mm);
                ffma2(A3, u1.y, mm);
            }
            float* P = halfp ? g_P2 : g_P1;
            if (qb+0<NQ) P[(qb+0)*D+jj]=ulo(A0);
            if (qb+1<NQ) P[(qb+1)*D+jj]=uhi(A0);
            if (qb+2<NQ) P[(qb+2)*D+jj]=ulo(A1);
            if (qb+3<NQ) P[(qb+3)*D+jj]=uhi(A1);
            if (qb+4<NQ) P[(qb+4)*D+jj]=ulo(A2);
            if (qb+5<NQ) P[(qb+5)*D+jj]=uhi(A2);
            if (qb+6<NQ) P[(qb+6)*D+jj]=ulo(A3);
            if (qb+7<NQ) P[(qb+7)*D+jj]=uhi(A3);
        }

        if (qb+w < NQ){
            float e0=E8[(lane   )*8+w];
            float e1=E8[(lane+32)*8+w];
            float e2=E8[(lane+64)*8+w];
            float e3=E8[(lane+96)*8+w];
            float d0 = e0*x00 + e1*x01 + e2*x02 + e3*x03;
            float d1 = e0*x10 + e1*x11 + e2*x12 + e3*x13;
            float d2 = e0*x20 + e1*x21 + e2*x22 + e3*x23;
            float d3 = e0*x30 + e1*x31 + e2*x32 + e3*x33;
            float nrm = e0*e0+e1*e1+e2*e2+e3*e3;
            #pragma unroll
            for (int off=16; off; off>>=1){
                d0  += __shfl_down_sync(0xffffffffu, d0, off);
                d1  += __shfl_down_sync(0xffffffffu, d1, off);
                d2  += __shfl_down_sync(0xffffffffu, d2, off);
                d3  += __shfl_down_sync(0xffffffffu, d3, off);
                nrm += __shfl_down_sync(0xffffffffu, nrm, off);
            }
            if (lane==0){
                float rq = 1.f/fmaxf(sqrtf(nrm), 1e-8f);
                g_qdm[qb+w] = 0.5f*rq*(d0*rn0C*m0C + d1*rn1C*m1C + d2*rn2C*m2C + d3*rn3C*m3C)
                            + 0.5f*(m0C+m1C+m2C+m3C);
            }
        }
        __syncthreads();
    }
}

// ---------------- scan: 2 batch rows per CTA (shared W regs, ILP across rows) ----------------
#define SCAN_THREADS 256   // warps 0..3 matvec (both rows), warps 4..7 output (2 per row)

// matvec step T for row R, consuming prefetch set (P1v..ITv) loaded at T-2; reload for T+2
#define MV_STEP_ROW(R, T, P1v,P2v,UTv,HAv,ITv) do{                                      \
    float curP1_=P1v, curP2_=P2v, curUT_=UTv, curHA_=HAv, curIT_=ITv;                   \
    int tp_ = (T)+2; if (tp_ > S-1) tp_ = S-1;                                          \
    int qp_ = sq[R][tp_];                                                               \
    P1v = __ldg(&g_P1[qp_*D+j]);                                                        \
    P2v = __ldg(&g_P2[qp_*D+j]);                                                        \
    UTv = __ldg(&g_UT[sut[R][tp_]*D+j]);                                                \
    HAv = __ldg(&g_HA[sha[R][tp_]*D+j]);                                                \
    ITv = __ldg(&g_IT[sit[R][tp_]*D+j]);                                                \
    float ctv_   = (float)sc[R][T];                                                     \
    float basea_ = curP1_ + ctv_*rv1 + curUT_ + curHA_ + rbA;                           \
    float basez_ = curP2_ + ctv_*rv2 + curIT_ + rbF;                                    \
    const float* lprev_ = lring[R][((T)+3)&3];                                          \
    float lpj_ = lprev_[j];                                                             \
    const ulonglong2* xp_ = (const ulonglong2*)lprev_;                                  \
    unsigned long long a0_=0ull,a1_=0ull,a2_=0ull,a3_=0ull;                             \
    _Pragma("unroll")                                                                   \
    for (int i_=0; i_<32; i_+=2){                                                       \
        ulonglong2 v0_ = xp_[i_];                                                       \
        ulonglong2 v1_ = xp_[i_+1];                                                     \
        ffma2(a0_, v0_.x, w2[2*i_  ]);                                                  \
        ffma2(a1_, v0_.y, w2[2*i_+1]);                                                  \
        ffma2(a2_, v1_.x, w2[2*i_+2]);                                                  \
        ffma2(a3_, v1_.y, w2[2*i_+3]);                                                  \
    }                                                                                   \
    fadd2(a0_,a1_); fadd2(a2_,a3_); fadd2(a0_,a2_);                                     \
    float z_ = (ulo(a0_) + uhi(a0_)) + basez_;                                          \
    float f_ = 1.f/(1.f+__expf(-z_));                                                   \
    lring[R][(T)&3][j] = lpj_*f_ + basea_;                                              \
}while(0)

#define OW_LOAD_SET(SFX, o) do{                                                          \
    int q1_ = sqo[(o)+1];                                                                \
    int4 cid_ = __ldg((const int4*)q2c + q1_);                                           \
    const float* e0_ = EC + cid_.x*D + lane;                                             \
    const float* e1_ = EC + cid_.y*D + lane;                                             \
    const float* e2_ = EC + cid_.z*D + lane;                                             \
    const float* e3_ = EC + cid_.w*D + lane;                                             \
    E##SFX[0]=e0_[0];  E##SFX[1]=e0_[32];  E##SFX[2]=e0_[64];  E##SFX[3]=e0_[96];        \
    E##SFX[4]=e1_[0];  E##SFX[5]=e1_[32];  E##SFX[6]=e1_[64];  E##SFX[7]=e1_[96];        \
    E##SFX[8]=e2_[0];  E##SFX[9]=e2_[32];  E##SFX[10]=e2_[64]; E##SFX[11]=e2_[96];       \
    E##SFX[12]=e3_[0]; E##SFX[13]=e3_[32]; E##SFX[14]=e3_[64]; E##SFX[15]=e3_[96];       \
    if (lane==0){                                                                        \
        rn0##SFX=g_rnC[cid_.x]; rn1##SFX=g_rnC[cid_.y];                                  \
        rn2##SFX=g_rnC[cid_.z]; rn3##SFX=g_rnC[cid_.w];                                  \
        qd##SFX=g_qd[q1_];                                                               \
        int qt_ = sqo[o]; qdm##SFX=g_qdm[qt_];                                           \
        int4 mm_ = __ldg((const int4*)q2cm + qt_);                                       \
        m0##SFX=(float)mm_.x; m1##SFX=(float)mm_.y;                                      \
        m2##SFX=(float)mm_.z; m3##SFX=(float)mm_.w;                                      \
    }                                                                                    \
}while(0)

#define OW_EMIT_SET(SFX, o) do{                                                          \
    const float* lcv_ = lrow[(o)&3];                                                     \
    float x0_=lcv_[lane], x1_=lcv_[lane+32], x2_=lcv_[lane+64], x3_=lcv_[lane+96];       \
    float d0_ = x0_*E##SFX[0]  + x1_*E##SFX[1]  + x2_*E##SFX[2]  + x3_*E##SFX[3];        \
    float d1_ = x0_*E##SFX[4]  + x1_*E##SFX[5]  + x2_*E##SFX[6]  + x3_*E##SFX[7];        \
    float d2_ = x0_*E##SFX[8]  + x1_*E##SFX[9]  + x2_*E##SFX[10] + x3_*E##SFX[11];       \
    float d3_ = x0_*E##SFX[12] + x1_*E##SFX[13] + x2_*E##SFX[14] + x3_*E##SFX[15];       \
    float nv_ = x0_*x0_ + x1_*x1_ + x2_*x2_ + x3_*x3_;                                   \
    _Pragma("unroll")                                                                    \
    for (int o_=16;o_;o_>>=1){                                                           \
        d0_ += __shfl_down_sync(0xffffffffu, d0_, o_);                                   \
        d1_ += __shfl_down_sync(0xffffffffu, d1_, o_);                                   \
        d2_ += __shfl_down_sync(0xffffffffu, d2_, o_);                                   \
        d3_ += __shfl_down_sync(0xffffffffu, d3_, o_);                                   \
        nv_ += __shfl_down_sync(0xffffffffu, nv_, o_);                                   \
    }                                                                                    \
    if (lane==0){                                                                        \
        float rl_ = 1.f/fmaxf(sqrtf(nv_), 1e-8f);                                        \
        float ss_ = 0.5f*((d0_*rn0##SFX*rl_+1.f)*m0##SFX + (d1_*rn1##SFX*rl_+1.f)*m1##SFX\
                        + (d2_*rn2##SFX*rl_+1.f)*m2##SFX + (d3_*rn3##SFX*rl_+1.f)*m3##SFX);\
        float lg_ = qd##SFX*(ss_ - qdm##SFX);                                            \
        outo[o] = 1.f/(1.f+__expf(-lg_));                                                \
    }                                                                                    \
}while(0)

#define OW_EVEN(T) do{                                                                   \
    int o_ = (T) + p;                                                                    \
    if (o_ <= S-2){                                                                      \
        if ((((T)>>1)&1)==0) OW_LOAD_SET(A, o_);                                         \
        else                 OW_LOAD_SET(B, o_);                                         \
    }                                                                                    \
}while(0)

#define OW_ODD(T) do{                                                                    \
    if ((T) >= 3){                                                                       \
        int o_ = (T)-3+p;                                                                \
        if (((((T)-3)>>1)&1)==0) OW_EMIT_SET(A, o_);                                     \
        else                     OW_EMIT_SET(B, o_);                                     \
    }                                                                                    \
}while(0)

__global__ void __launch_bounds__(SCAN_THREADS,1) scan_kernel(
    const int* __restrict__ qseq, const int* __restrict__ haseq,
    const int* __restrict__ cseq, const int* __restrict__ itseq,
    const int* __restrict__ utseq,
    const int* __restrict__ q2c, const int* __restrict__ q2cm,
    const float* __restrict__ EC, const float* __restrict__ Wfor,
    const float* __restrict__ lat0, float* __restrict__ out)
{
    __shared__ __align__(16) float lring[2][4][D];  // per-row ring; slot 3 = latent0
    __shared__ int sq[2][S], sha[2][S], sc[2][S], sit[2][S], sut[2][S];

    const int bid  = blockIdx.x;
    const int r0   = 2*bid;              // global rows r0, r0+1
    const int tid  = threadIdx.x;
    const int lane = tid & 31;
    const bool ow  = (tid >= 128);
    const int j    = tid;                // matvec column (valid when !ow)
    const int oww  = (tid>>5) - 4;       // output warp 0..3
    const int rw   = oww >> 1;           // output row (0/1)
    const int p    = oww & 1;            // output parity

    if (tid < S){
        #pragma unroll
        for (int r=0; r<2; r++){
            sq[r][tid]=qseq[(r0+r)*S+tid]; sha[r][tid]=haseq[(r0+r)*S+tid];
            sc[r][tid]=cseq[(r0+r)*S+tid]; sit[r][tid]=itseq[(r0+r)*S+tid];
            sut[r][tid]=utseq[(r0+r)*S+tid];
        }
    }
    if (tid < D){
        lring[0][3][tid] = lat0[r0*D+tid];
        lring[1][3][tid] = lat0[(r0+1)*D+tid];
    }

    unsigned long long w2[64];
    float rv1=0.f, rv2=0.f, rbA=0.f, rbF=0.f;
    if (!ow){
        #pragma unroll
        for (int kk=0; kk<64; kk++){
            unsigned lo = __float_as_uint(Wfor[(2*kk  )*D + j]);
            unsigned hi = __float_as_uint(Wfor[(2*kk+1)*D + j]);
            w2[kk] = ((unsigned long long)hi << 32) | lo;
        }
        rv1=g_v1[j]; rv2=g_v2[j]; rbA=g_bA[j]; rbF=g_bF[j];
    }
    __syncthreads();   // seqs + lring init visible

    // depth-2 prefetch per row: set A = even steps, set B = odd steps
    float pA1_0=0,pA2_0=0,pA3_0=0,pA4_0=0,pA5_0=0, pB1_0=0,pB2_0=0,pB3_0=0,pB4_0=0,pB5_0=0;
    float pA1_1=0,pA2_1=0,pA3_1=0,pA4_1=0,pA5_1=0, pB1_1=0,pB2_1=0,pB3_1=0,pB4_1=0,pB5_1=0;
    if (!ow){
        #pragma unroll
        for (int r=0; r<2; r++){
            int qa = sq[r][0], qb = sq[r][1];
            float a1=g_P1[qa*D+j], a2=g_P2[qa*D+j], a3=g_UT[sut[r][0]*D+j],
                  a4=g_HA[sha[r][0]*D+j], a5=g_IT[sit[r][0]*D+j];
            float b1=g_P1[qb*D+j], b2=g_P2[qb*D+j], b3=g_UT[sut[r][1]*D+j],
                  b4=g_HA[sha[r][1]*D+j], b5=g_IT[sit[r][1]*D+j];
            if (r==0){ pA1_0=a1;pA2_0=a2;pA3_0=a3;pA4_0=a4;pA5_0=a5;
                       pB1_0=b1;pB2_0=b2;pB3_0=b3;pB4_0=b4;pB5_0=b5; }
            else     { pA1_1=a1;pA2_1=a2;pA3_1=a3;pA4_1=a4;pA5_1=a5;
                       pB1_1=b1;pB2_1=b2;pB3_1=b3;pB4_1=b4;pB5_1=b5; }
        }
    }

    // output-warp per-row pointers
    const int* sqo = sq[rw & 1];
    float (*lrow)[D] = lring[rw & 1];
    float* outo = out + (r0 + (rw & 1))*S;

    float EA[16], EB[16];
    float rn0A=0,rn1A=0,rn2A=0,rn3A=0,qdA=0,qdmA=0,m0A=0,m1A=0,m2A=0,m3A=0;
    float rn0B=0,rn1B=0,rn2B=0,rn3B=0,qdB=0,qdmB=0,m0B=0,m1B=0,m2B=0,m3B=0;

    for (int t=0; t<S-2; t+=2){
        if (!ow){
            MV_STEP_ROW(0, t, pA1_0,pA2_0,pA3_0,pA4_0,pA5_0);
            MV_STEP_ROW(1, t, pA1_1,pA2_1,pA3_1,pA4_1,pA5_1);
            asm volatile("bar.sync 1, 128;" ::: "memory");
            MV_STEP_ROW(0, t+1, pB1_0,pB2_0,pB3_0,pB4_0,pB5_0);
            MV_STEP_ROW(1, t+1, pB1_1,pB2_1,pB3_1,pB4_1,pB5_1);
        } else {
            OW_EVEN(t);
            OW_ODD(t+1);
        }
        __syncthreads();
    }
    if (!ow){
        MV_STEP_ROW(0, S-2, pA1_0,pA2_0,pA3_0,pA4_0,pA5_0);
        MV_STEP_ROW(1, S-2, pA1_1,pA2_1,pA3_1,pA4_1,pA5_1);
    } else {
        OW_EVEN(S-2);
    }
    __syncthreads();

    // epilogue per output warp: outputs 196,197 (set A) and 198 (set B, p=0)
    if (ow){
        { int o = 196 + p; OW_EMIT_SET(A, o); }
        if (p == 0){ OW_EMIT_SET(B, 198); }
    }
    if (tid < 2) out[(r0+tid)*S + (S-1)] = 0.f;
}

extern "C" void kernel_launch(void* const* d_in, const int* in_sizes, int n_in,
                              void* d_out, int out_size)
{
    const int*   qseq  = (const int*)  d_in[0];
    const int*   haseq = (const int*)  d_in[1];
    const int*   cseq  = (const int*)  d_in[2];
    const int*   itseq = (const int*)  d_in[3];
    const int*   utseq = (const int*)  d_in[4];
    const int*   q2c   = (const int*)  d_in[5];
    const int*   q2cm  = (const int*)  d_in[6];
    const float* EQ    = (const float*)d_in[7];
    const float* EQd   = (const float*)d_in[8];
    const float* EC    = (const float*)d_in[9];
    const float* EIT   = (const float*)d_in[10];
    const float* EUT   = (const float*)d_in[11];
    const float* EHA   = (const float*)d_in[12];
    const float* Wfuse = (const float*)d_in[13];
    const float* bfuse = (const float*)d_in[14];
    const float* Wabs  = (const float*)d_in[15];
    const float* babs  = (const float*)d_in[16];
    const float* Wfor  = (const float*)d_in[17];
    const float* bfor  = (const float*)d_in[18];
    const float* lat0  = (const float*)d_in[19];
    float* out = (float*)d_out;

    cudaFuncSetAttribute(prepB_kernel,
                         cudaFuncAttributeMaxDynamicSharedMemorySize, SMEM_B);

    prepA_kernel<<<554, 128>>>(Wfuse, bfuse, Wabs, babs, Wfor, bfor,
                               EQd, EC, EIT, EUT, EHA);
    prepB_kernel<<<NBQ+2, 256, SMEM_B>>>(EQ, EC, q2c, q2cm, Wabs, Wfor);
    probe_kernel<<<1, 32>>>();
    scan_kernel<<<B/2, SCAN_THREADS>>>(qseq, haseq, cseq, itseq, utseq,
                                       q2c, q2cm, EC, Wfor, lat0, out);
}

// round 15
// speedup vs baseline: 1.3614x; 1.3614x over previous
#include <cuda_runtime.h>
#include <math.h>

#define D   128
#define B   128
#define S   200
#define NQ  10000
#define NC  500

// ---------------- scratch tables (device globals; no allocation) ----------------
__device__ float g_M1[D*D];      // W_fuse_top @ W_absorb_top
__device__ float g_M2[D*D];      // W_fuse_top @ W_forget_bot
__device__ float g_UT[100*D];    // embed_use_time @ W_absorb_mid
__device__ float g_HA[12*D];     // embed_hint_attempt @ W_absorb_bot
__device__ float g_IT[100*D];    // embed_interval_time @ W_forget_mid
__device__ float g_s1[D];        // colsum(W_fuse_bot)
__device__ float g_v1[D];        // s1 @ W_absorb_top
__device__ float g_v2[D];        // s1 @ W_forget_bot
__device__ float g_bA[D];        // b_fuse @ W_absorb_top + b_absorb
__device__ float g_bF[D];        // b_fuse @ W_forget_bot + b_forget
__device__ float g_P1[NQ*D];     // embed_question @ M1
__device__ float g_P2[NQ*D];     // embed_question @ M2
__device__ float g_qd[NQ];       // 10*sigmoid(disc)
__device__ float g_qdm[NQ];      // sum_k qdiff_k * mask_k  (per question)
__device__ float g_rnC[NC];      // 1/max(|concept|,eps)

// packed f32x2 ops (sm_100+)
__device__ __forceinline__ void ffma2(unsigned long long &d,
                                      unsigned long long a, unsigned long long b){
    asm("fma.rn.f32x2 %0, %1, %2, %0;" : "+l"(d) : "l"(a), "l"(b));
}
__device__ __forceinline__ void fadd2(unsigned long long &d, unsigned long long a){
    asm("add.rn.f32x2 %0, %0, %1;" : "+l"(d) : "l"(a));
}
__device__ __forceinline__ float ulo(unsigned long long v){ return __uint_as_float((unsigned)v); }
__device__ __forceinline__ float uhi(unsigned long long v){ return __uint_as_float((unsigned)(v>>32)); }
__device__ __forceinline__ unsigned long long dup2(float m){
    unsigned long long r; unsigned mb = __float_as_uint(m);
    asm("mov.b64 %0, {%1, %1};" : "=l"(r) : "r"(mb));
    return r;
}

// ---------------- prepA: 4-row grouped vec-mats (Wb reuse x4) + small tables ----------------
// blocks: [0,32) M1 | [32,64) M2 | [64,89) UT | [89,92) HA | [92,117) IT |
//         117 s1 | 118 bA | 119 bF | [120,124) rnC | [124,203) qd
__global__ void __launch_bounds__(128) prepA_kernel(
    const float* __restrict__ Wfuse, const float* __restrict__ bfuse,
    const float* __restrict__ Wabs,  const float* __restrict__ babs,
    const float* __restrict__ Wfor,  const float* __restrict__ bfor,
    const float* __restrict__ EQd,   const float* __restrict__ EC,
    const float* __restrict__ EIT,   const float* __restrict__ EUT,
    const float* __restrict__ EHA)
{
    __shared__ float sh[4][D];
    const int tid = threadIdx.x;
    const int bid = blockIdx.x;

    if (bid < 117) {
        const float* vsrc; const float* Wb; float* outp;
        int row0, nrows;
        if (bid < 32)      { vsrc=Wfuse; Wb=Wabs;         outp=g_M1; row0=4*bid;      nrows=4; }
        else if (bid < 64) { vsrc=Wfuse; Wb=Wfor+2*D*D;   outp=g_M2; row0=4*(bid-32); nrows=4; }
        else if (bid < 89) { vsrc=EUT;   Wb=Wabs+D*D;     outp=g_UT; row0=4*(bid-64); nrows=4; }
        else if (bid < 92) { vsrc=EHA;   Wb=Wabs+2*D*D;   outp=g_HA; row0=4*(bid-89); nrows=(row0+4<=12)?4:(12-row0); }
        else               { vsrc=EIT;   Wb=Wfor+D*D;     outp=g_IT; row0=4*(bid-92); nrows=4; }
        for (int i=tid; i<4*D; i+=128){
            int r = i>>7, c = i&127;
            sh[r][c] = (r<nrows) ? vsrc[(row0+r)*D+c] : 0.f;
        }
        __syncthreads();
        float a0=0.f,a1=0.f,a2=0.f,a3=0.f;
        #pragma unroll 8
        for (int jj=0; jj<D; jj++){
            float w = __ldg(&Wb[jj*D+tid]);
            a0 += sh[0][jj]*w;
            a1 += sh[1][jj]*w;
            a2 += sh[2][jj]*w;
            a3 += sh[3][jj]*w;
        }
        outp[(row0+0)*D+tid] = a0;
        if (nrows>1) outp[(row0+1)*D+tid] = a1;
        if (nrows>2) outp[(row0+2)*D+tid] = a2;
        if (nrows>3) outp[(row0+3)*D+tid] = a3;
    } else if (bid == 117) {
        float a0=0.f,a1=0.f,a2=0.f,a3=0.f;
        #pragma unroll
        for (int k=0;k<D;k+=4){
            a0 += Wfuse[(D+k+0)*D+tid]; a1 += Wfuse[(D+k+1)*D+tid];
            a2 += Wfuse[(D+k+2)*D+tid]; a3 += Wfuse[(D+k+3)*D+tid];
        }
        g_s1[tid]=(a0+a1)+(a2+a3);
    } else if (bid == 118) {
        sh[0][tid]=bfuse[tid]; __syncthreads();
        float a0=0.f,a1=0.f,a2=0.f,a3=0.f;
        #pragma unroll
        for (int k=0;k<D;k+=4){
            a0 += sh[0][k+0]*Wabs[(k+0)*D+tid]; a1 += sh[0][k+1]*Wabs[(k+1)*D+tid];
            a2 += sh[0][k+2]*Wabs[(k+2)*D+tid]; a3 += sh[0][k+3]*Wabs[(k+3)*D+tid];
        }
        g_bA[tid] = (a0+a1)+(a2+a3) + babs[tid];
    } else if (bid == 119) {
        sh[0][tid]=bfuse[tid]; __syncthreads();
        float a0=0.f,a1=0.f,a2=0.f,a3=0.f;
        #pragma unroll
        for (int k=0;k<D;k+=4){
            a0 += sh[0][k+0]*Wfor[(2*D+k+0)*D+tid]; a1 += sh[0][k+1]*Wfor[(2*D+k+1)*D+tid];
            a2 += sh[0][k+2]*Wfor[(2*D+k+2)*D+tid]; a3 += sh[0][k+3]*Wfor[(2*D+k+3)*D+tid];
        }
        g_bF[tid] = (a0+a1)+(a2+a3) + bfor[tid];
    } else if (bid < 124) {
        int c = (bid-120)*128 + tid;
        if (c < NC){
            float s=0.f;
            #pragma unroll
            for (int dd=0; dd<D; dd+=4){
                float4 e = *(const float4*)&EC[c*D+dd];
                s += e.x*e.x + e.y*e.y + e.z*e.z + e.w*e.w;
            }
            g_rnC[c] = 1.f/fmaxf(sqrtf(s), 1e-8f);
        }
    } else {
        int q = (bid-124)*128 + tid;
        if (q < NQ) g_qd[q] = 10.f/(1.f+__expf(-EQd[q]));
    }
}

// ---------------- prepB: 8-question tiles, f32x2-packed, balanced qdm ----------------
#define NBQ 139
#define QPB 72
#define SMEM_B ((2*D*D + 8*D) * (int)sizeof(float))

__global__ void __launch_bounds__(256) prepB_kernel(
    const float* __restrict__ EQ, const float* __restrict__ EC,
    const int* __restrict__ q2c, const int* __restrict__ q2cm,
    const float* __restrict__ Wabs, const float* __restrict__ Wfor)
{
    const int tid = threadIdx.x;
    const int bid = blockIdx.x;

    if (bid >= NBQ){                       // v1 / v2 blocks (need g_s1 from prepA)
        __shared__ float s1s[D];
        if (tid < D) s1s[tid] = g_s1[tid];
        __syncthreads();
        if (tid < D){
            const float* Wb = (bid==NBQ) ? Wabs : (Wfor + 2*D*D);
            float a0=0.f,a1=0.f,a2=0.f,a3=0.f;
            #pragma unroll
            for (int jj=0;jj<D;jj+=4){
                a0 += s1s[jj+0]*Wb[(jj+0)*D+tid]; a1 += s1s[jj+1]*Wb[(jj+1)*D+tid];
                a2 += s1s[jj+2]*Wb[(jj+2)*D+tid]; a3 += s1s[jj+3]*Wb[(jj+3)*D+tid];
            }
            float a = (a0+a1)+(a2+a3);
            if (bid==NBQ) g_v1[tid]=a; else g_v2[tid]=a;
        }
        return;
    }

    extern __shared__ float smem[];
    float* M1s = smem;            // D*D
    float* M2s = smem + D*D;      // D*D
    float* E8  = smem + 2*D*D;    // 8 questions interleaved: E8[jj*8+q]

    const int w    = tid>>5;      // warp 0..7 — qdm question slot
    const int lane = tid&31;
    const int eq   = tid&7;       // E-staging question slot
    const int eg   = tid>>3;      // E-staging jj group (0..31)

    for (int i=tid; i<D*D; i+=256){ M1s[i]=g_M1[i]; M2s[i]=g_M2[i]; }

    const int qbase = bid*QPB;

    float4 eR = make_float4(0.f,0.f,0.f,0.f);
    { int q = qbase+eq; if (q<NQ) eR = *(const float4*)&EQ[q*D + eg*4]; }
    int4 cidN = make_int4(0,0,0,0);
    float rn0N=0,rn1N=0,rn2N=0,rn3N=0,m0N=0,m1N=0,m2N=0,m3N=0;
    { int q = qbase+w;
      if (q<NQ){
        cidN = ((const int4*)q2c)[q];
        rn0N=g_rnC[cidN.x]; rn1N=g_rnC[cidN.y]; rn2N=g_rnC[cidN.z]; rn3N=g_rnC[cidN.w];
        int4 mm = ((const int4*)q2cm)[q];
        m0N=(float)mm.x; m1N=(float)mm.y; m2N=(float)mm.z; m3N=(float)mm.w;
      }
    }
    __syncthreads();   // M1s/M2s visible

    for (int tt=0; tt<9; tt++){
        const int qb = qbase + tt*8;
        {
            int jb = eg*4;
            E8[(jb+0)*8+eq]=eR.x; E8[(jb+1)*8+eq]=eR.y;
            E8[(jb+2)*8+eq]=eR.z; E8[(jb+3)*8+eq]=eR.w;
        }
        const int4  cidC = cidN;
        const float rn0C=rn0N, rn1C=rn1N, rn2C=rn2N, rn3C=rn3N;
        const float m0C=m0N, m1C=m1N, m2C=m2N, m3C=m3N;
        __syncthreads();

        if (tt<8){
            int q = qb+8+eq;
            eR = make_float4(0.f,0.f,0.f,0.f);
            if (q<NQ) eR = *(const float4*)&EQ[q*D + eg*4];
            int qm = qb+8+w;
            if (qm<NQ){
                cidN = ((const int4*)q2c)[qm];
                rn0N=g_rnC[cidN.x]; rn1N=g_rnC[cidN.y]; rn2N=g_rnC[cidN.z]; rn3N=g_rnC[cidN.w];
                int4 mm = ((const int4*)q2cm)[qm];
                m0N=(float)mm.x; m1N=(float)mm.y; m2N=(float)mm.z; m3N=(float)mm.w;
            }
        }

        const float* ec0 = EC + cidC.x*D + lane;
        const float* ec1 = EC + cidC.y*D + lane;
        const float* ec2 = EC + cidC.z*D + lane;
        const float* ec3 = EC + cidC.w*D + lane;
        float x00=ec0[0], x01=ec0[32], x02=ec0[64], x03=ec0[96];
        float x10=ec1[0], x11=ec1[32], x12=ec1[64], x13=ec1[96];
        float x20=ec2[0], x21=ec2[32], x22=ec2[64], x23=ec2[96];
        float x30=ec3[0], x31=ec3[32], x32=ec3[64], x33=ec3[96];

        {
            const int halfp = tid>>7, jj = tid&127;
            const float* Ms = halfp ? M2s : M1s;
            unsigned long long A0=0ull,A1=0ull,A2=0ull,A3=0ull;
            const ulonglong2* Ev = (const ulonglong2*)E8;
            #pragma unroll 8
            for (int jk=0; jk<D; jk++){
                ulonglong2 u0 = Ev[jk*2];
                ulonglong2 u1 = Ev[jk*2+1];
                unsigned long long mm = dup2(Ms[jk*D+jj]);
                ffma2(A0, u0.x, mm);
                ffma2(A1, u0.y, mm);
                ffma2(A2, u1.x, mm);
                ffma2(A3, u1.y, mm);
            }
            float* P = halfp ? g_P2 : g_P1;
            if (qb+0<NQ) P[(qb+0)*D+jj]=ulo(A0);
            if (qb+1<NQ) P[(qb+1)*D+jj]=uhi(A0);
            if (qb+2<NQ) P[(qb+2)*D+jj]=ulo(A1);
            if (qb+3<NQ) P[(qb+3)*D+jj]=uhi(A1);
            if (qb+4<NQ) P[(qb+4)*D+jj]=ulo(A2);
            if (qb+5<NQ) P[(qb+5)*D+jj]=uhi(A2);
            if (qb+6<NQ) P[(qb+6)*D+jj]=ulo(A3);
            if (qb+7<NQ) P[(qb+7)*D+jj]=uhi(A3);
        }

        if (qb+w < NQ){
            float e0=E8[(lane   )*8+w];
            float e1=E8[(lane+32)*8+w];
            float e2=E8[(lane+64)*8+w];
            float e3=E8[(lane+96)*8+w];
            float d0 = e0*x00 + e1*x01 + e2*x02 + e3*x03;
            float d1 = e0*x10 + e1*x11 + e2*x12 + e3*x13;
            float d2 = e0*x20 + e1*x21 + e2*x22 + e3*x23;
            float d3 = e0*x30 + e1*x31 + e2*x32 + e3*x33;
            float nrm = e0*e0+e1*e1+e2*e2+e3*e3;
            #pragma unroll
            for (int off=16; off; off>>=1){
                d0  += __shfl_down_sync(0xffffffffu, d0, off);
                d1  += __shfl_down_sync(0xffffffffu, d1, off);
                d2  += __shfl_down_sync(0xffffffffu, d2, off);
                d3  += __shfl_down_sync(0xffffffffu, d3, off);
                nrm += __shfl_down_sync(0xffffffffu, nrm, off);
            }
            if (lane==0){
                float rq = 1.f/fmaxf(sqrtf(nrm), 1e-8f);
                g_qdm[qb+w] = 0.5f*rq*(d0*rn0C*m0C + d1*rn1C*m1C + d2*rn2C*m2C + d3*rn3C*m3C)
                            + 0.5f*(m0C+m1C+m2C+m3C);
            }
        }
        __syncthreads();
    }
}

// ---------------- scan: round-12 structure (best measured: 107.5us) ----------------
#define SCAN_THREADS 192   // warps 0..3 matvec (1 column/thread), warps 4..5 output

#define MV_STEP(T, P1v,P2v,UTv,HAv,ITv, DO_BAR) do{                                      \
    float curP1_=P1v, curP2_=P2v, curUT_=UTv, curHA_=HAv, curIT_=ITv;                    \
    int tp_ = (T)+2; if (tp_ > S-1) tp_ = S-1;                                           \
    int qp_ = sq[tp_];                                                                   \
    P1v = __ldg(&g_P1[qp_*D+j]);                                                         \
    P2v = __ldg(&g_P2[qp_*D+j]);                                                         \
    UTv = __ldg(&g_UT[sut[tp_]*D+j]);                                                    \
    HAv = __ldg(&g_HA[sha[tp_]*D+j]);                                                    \
    ITv = __ldg(&g_IT[sit[tp_]*D+j]);                                                    \
    float ctv_   = (float)sc[T];                                                         \
    float basea_ = curP1_ + ctv_*rv1 + curUT_ + curHA_ + rbA;                            \
    float basez_ = curP2_ + ctv_*rv2 + curIT_ + rbF;                                     \
    const float* lprev_ = lring[((T)+3)&3];                                              \
    float lpj_ = lprev_[j];                                                              \
    const ulonglong2* xp_ = (const ulonglong2*)lprev_;                                   \
    unsigned long long a0_=0ull,a1_=0ull,a2_=0ull,a3_=0ull;                              \
    _Pragma("unroll")                                                                    \
    for (int i_=0; i_<32; i_+=2){                                                        \
        ulonglong2 v0_ = xp_[i_];                                                        \
        ulonglong2 v1_ = xp_[i_+1];                                                      \
        ffma2(a0_, v0_.x, w2[2*i_  ]);                                                   \
        ffma2(a1_, v0_.y, w2[2*i_+1]);                                                   \
        ffma2(a2_, v1_.x, w2[2*i_+2]);                                                   \
        ffma2(a3_, v1_.y, w2[2*i_+3]);                                                   \
    }                                                                                    \
    fadd2(a0_,a1_); fadd2(a2_,a3_); fadd2(a0_,a2_);                                      \
    float z_ = (ulo(a0_) + uhi(a0_)) + basez_;                                           \
    float f_ = 1.f/(1.f+__expf(-z_));                                                    \
    lring[(T)&3][j] = lpj_*f_ + basea_;                                                  \
    if (DO_BAR) asm volatile("bar.sync 1, 128;" ::: "memory");                           \
}while(0)

#define OW_LOAD_SET(SFX, o) do{                                                          \
    int q1_ = sq[(o)+1];                                                                 \
    int4 cid_ = __ldg((const int4*)q2c + q1_);                                           \
    const float* e0_ = EC + cid_.x*D + lane;                                             \
    const float* e1_ = EC + cid_.y*D + lane;                                             \
    const float* e2_ = EC + cid_.z*D + lane;                                             \
    const float* e3_ = EC + cid_.w*D + lane;                                             \
    E##SFX[0]=e0_[0];  E##SFX[1]=e0_[32];  E##SFX[2]=e0_[64];  E##SFX[3]=e0_[96];        \
    E##SFX[4]=e1_[0];  E##SFX[5]=e1_[32];  E##SFX[6]=e1_[64];  E##SFX[7]=e1_[96];        \
    E##SFX[8]=e2_[0];  E##SFX[9]=e2_[32];  E##SFX[10]=e2_[64]; E##SFX[11]=e2_[96];       \
    E##SFX[12]=e3_[0]; E##SFX[13]=e3_[32]; E##SFX[14]=e3_[64]; E##SFX[15]=e3_[96];       \
    if (lane==0){                                                                        \
        rn0##SFX=g_rnC[cid_.x]; rn1##SFX=g_rnC[cid_.y];                                  \
        rn2##SFX=g_rnC[cid_.z]; rn3##SFX=g_rnC[cid_.w];                                  \
        qd##SFX=g_qd[q1_];                                                               \
        int qt_ = sq[o]; qdm##SFX=g_qdm[qt_];                                            \
        int4 mm_ = __ldg((const int4*)q2cm + qt_);                                       \
        m0##SFX=(float)mm_.x; m1##SFX=(float)mm_.y;                                      \
        m2##SFX=(float)mm_.z; m3##SFX=(float)mm_.w;                                      \
    }                                                                                    \
}while(0)

#define OW_EMIT_SET(SFX, o) do{                                                          \
    const float* lcv_ = lring[(o)&3];                                                    \
    float x0_=lcv_[lane], x1_=lcv_[lane+32], x2_=lcv_[lane+64], x3_=lcv_[lane+96];       \
    float d0_ = x0_*E##SFX[0]  + x1_*E##SFX[1]  + x2_*E##SFX[2]  + x3_*E##SFX[3];        \
    float d1_ = x0_*E##SFX[4]  + x1_*E##SFX[5]  + x2_*E##SFX[6]  + x3_*E##SFX[7];        \
    float d2_ = x0_*E##SFX[8]  + x1_*E##SFX[9]  + x2_*E##SFX[10] + x3_*E##SFX[11];       \
    float d3_ = x0_*E##SFX[12] + x1_*E##SFX[13] + x2_*E##SFX[14] + x3_*E##SFX[15];       \
    float nv_ = x0_*x0_ + x1_*x1_ + x2_*x2_ + x3_*x3_;                                   \
    _Pragma("unroll")                                                                    \
    for (int o_=16;o_;o_>>=1){                                                           \
        d0_ += __shfl_down_sync(0xffffffffu, d0_, o_);                                   \
        d1_ += __shfl_down_sync(0xffffffffu, d1_, o_);                                   \
        d2_ += __shfl_down_sync(0xffffffffu, d2_, o_);                                   \
        d3_ += __shfl_down_sync(0xffffffffu, d3_, o_);                                   \
        nv_ += __shfl_down_sync(0xffffffffu, nv_, o_);                                   \
    }                                                                                    \
    if (lane==0){                                                                        \
        float rl_ = 1.f/fmaxf(sqrtf(nv_), 1e-8f);                                        \
        float ss_ = 0.5f*((d0_*rn0##SFX*rl_+1.f)*m0##SFX + (d1_*rn1##SFX*rl_+1.f)*m1##SFX\
                        + (d2_*rn2##SFX*rl_+1.f)*m2##SFX + (d3_*rn3##SFX*rl_+1.f)*m3##SFX);\
        float lg_ = qd##SFX*(ss_ - qdm##SFX);                                            \
        out[b*S+(o)] = 1.f/(1.f+__expf(-lg_));                                           \
    }                                                                                    \
}while(0)

#define OW_EVEN(T) do{                                                                   \
    int o_ = (T) + p;                                                                    \
    if (o_ <= S-2){                                                                      \
        if ((((T)>>1)&1)==0) OW_LOAD_SET(A, o_);                                         \
        else                 OW_LOAD_SET(B, o_);                                         \
    }                                                                                    \
}while(0)

#define OW_ODD(T) do{                                                                    \
    if ((T) >= 3){                                                                       \
        int o_ = (T)-3+p;                                                                \
        if (((((T)-3)>>1)&1)==0) OW_EMIT_SET(A, o_);                                     \
        else                     OW_EMIT_SET(B, o_);                                     \
    }                                                                                    \
}while(0)

__global__ void __launch_bounds__(SCAN_THREADS,1) scan_kernel(
    const int* __restrict__ qseq, const int* __restrict__ haseq,
    const int* __restrict__ cseq, const int* __restrict__ itseq,
    const int* __restrict__ utseq,
    const int* __restrict__ q2c, const int* __restrict__ q2cm,
    const float* __restrict__ EC, const float* __restrict__ Wfor,
    const float* __restrict__ lat0, float* __restrict__ out)
{
    __shared__ __align__(16) float lring[4][D];   // slot t&3 = lc_t; slot 3 init = latent0
    __shared__ int sq[S], sha[S], sc[S], sit[S], sut[S];

    const int b    = blockIdx.x;
    const int tid  = threadIdx.x;
    const int lane = tid & 31;
    const bool ow  = (tid >= 128);
    const int j    = tid;               // matvec column (only valid when !ow)
    const int p    = (tid>>5) - 4;      // output warp parity (0/1)

    for (int i=tid; i<S; i+=SCAN_THREADS){
        sq[i]=qseq[b*S+i]; sha[i]=haseq[b*S+i]; sc[i]=cseq[b*S+i];
        sit[i]=itseq[b*S+i]; sut[i]=utseq[b*S+i];
    }
    if (tid < D) lring[3][tid] = lat0[b*D+tid];

    unsigned long long w2[64];
    float rv1=0.f, rv2=0.f, rbA=0.f, rbF=0.f;
    if (!ow){
        #pragma unroll
        for (int kk=0; kk<64; kk++){
            unsigned lo = __float_as_uint(Wfor[(2*kk  )*D + j]);
            unsigned hi = __float_as_uint(Wfor[(2*kk+1)*D + j]);
            w2[kk] = ((unsigned long long)hi << 32) | lo;
        }
        rv1=g_v1[j]; rv2=g_v2[j]; rbA=g_bA[j]; rbF=g_bF[j];
    }
    __syncthreads();   // seqs + lring[3] visible

    // depth-2 prefetch: set A = even steps, set B = odd steps
    float pA1=0,pA2=0,pA3=0,pA4=0,pA5=0;
    float pB1=0,pB2=0,pB3=0,pB4=0,pB5=0;
    if (!ow){
        int q0 = sq[0];
        pA1 = g_P1[q0*D+j]; pA2 = g_P2[q0*D+j];
        pA3 = g_UT[sut[0]*D+j]; pA4 = g_HA[sha[0]*D+j]; pA5 = g_IT[sit[0]*D+j];
        int q1 = sq[1];
        pB1 = g_P1[q1*D+j]; pB2 = g_P2[q1*D+j];
        pB3 = g_UT[sut[1]*D+j]; pB4 = g_HA[sha[1]*D+j]; pB5 = g_IT[sit[1]*D+j];
    }

    float EA[16], EB[16];
    float rn0A=0,rn1A=0,rn2A=0,rn3A=0,qdA=0,qdmA=0,m0A=0,m1A=0,m2A=0,m3A=0;
    float rn0B=0,rn1B=0,rn2B=0,rn3B=0,qdB=0,qdmB=0,m0B=0,m1B=0,m2B=0,m3B=0;

    for (int t=0; t<S-2; t+=2){
        if (!ow) MV_STEP(t,   pA1,pA2,pA3,pA4,pA5, 1);
        else     OW_EVEN(t);
        if (!ow) MV_STEP(t+1, pB1,pB2,pB3,pB4,pB5, 0);
        else     OW_ODD(t+1);
        __syncthreads();
    }
    if (!ow) MV_STEP(S-2, pA1,pA2,pA3,pA4,pA5, 0);
    else     OW_EVEN(S-2);
    __syncthreads();

    if (ow){
        { int o = 196 + p; OW_EMIT_SET(A, o); }
        if (p == 0){ OW_EMIT_SET(B, 198); }
    }
    if (tid==0) out[b*S + (S-1)] = 0.f;
}

extern "C" void kernel_launch(void* const* d_in, const int* in_sizes, int n_in,
                              void* d_out, int out_size)
{
    const int*   qseq  = (const int*)  d_in[0];
    const int*   haseq = (const int*)  d_in[1];
    const int*   cseq  = (const int*)  d_in[2];
    const int*   itseq = (const int*)  d_in[3];
    const int*   utseq = (const int*)  d_in[4];
    const int*   q2c   = (const int*)  d_in[5];
    const int*   q2cm  = (const int*)  d_in[6];
    const float* EQ    = (const float*)d_in[7];
    const float* EQd   = (const float*)d_in[8];
    const float* EC    = (const float*)d_in[9];
    const float* EIT   = (const float*)d_in[10];
    const float* EUT   = (const float*)d_in[11];
    const float* EHA   = (const float*)d_in[12];
    const float* Wfuse = (const float*)d_in[13];
    const float* bfuse = (const float*)d_in[14];
    const float* Wabs  = (const float*)d_in[15];
    const float* babs  = (const float*)d_in[16];
    const float* Wfor  = (const float*)d_in[17];
    const float* bfor  = (const float*)d_in[18];
    const float* lat0  = (const float*)d_in[19];
    float* out = (float*)d_out;

    cudaFuncSetAttribute(prepB_kernel,
                         cudaFuncAttributeMaxDynamicSharedMemorySize, SMEM_B);

    prepA_kernel<<<203, 128>>>(Wfuse, bfuse, Wabs, babs, Wfor, bfor,
                               EQd, EC, EIT, EUT, EHA);
    prepB_kernel<<<NBQ+2, 256, SMEM_B>>>(EQ, EC, q2c, q2cm, Wabs, Wfor);
    scan_kernel<<<B, SCAN_THREADS>>>(qseq, haseq, cseq, itseq, utseq,
                                     q2c, q2cm, EC, Wfor, lat0, out);
}

// round 16
// speedup vs baseline: 1.3950x; 1.0247x over previous
#include <cuda_runtime.h>
#include <math.h>

#define D   128
#define B   128
#define S   200
#define NQ  10000
#define NC  500

// ---------------- scratch tables (device globals; no allocation) ----------------
__device__ float g_M1[D*D];      // W_fuse_top @ W_absorb_top
__device__ float g_M2[D*D];      // W_fuse_top @ W_forget_bot
__device__ float g_UT[100*D];    // embed_use_time @ W_absorb_mid
__device__ float g_HA[12*D];     // embed_hint_attempt @ W_absorb_bot
__device__ float g_IT[100*D];    // embed_interval_time @ W_forget_mid
__device__ float g_s1[D];        // colsum(W_fuse_bot)
__device__ float g_v1[D];        // s1 @ W_absorb_top
__device__ float g_v2[D];        // s1 @ W_forget_bot
__device__ float g_bA[D];        // b_fuse @ W_absorb_top + b_absorb
__device__ float g_bF[D];        // b_fuse @ W_forget_bot + b_forget
__device__ float g_P12[NQ*D*2];  // interleaved: [q][j][0]=P1, [q][j][1]=P2
__device__ float g_qd[NQ];       // 10*sigmoid(disc)
__device__ float g_qdm[NQ];      // sum_k qdiff_k * mask_k  (per question)
__device__ float g_rnC[NC];      // 1/max(|concept|,eps)

// packed f32x2 ops (sm_100+)
__device__ __forceinline__ void ffma2(unsigned long long &d,
                                      unsigned long long a, unsigned long long b){
    asm("fma.rn.f32x2 %0, %1, %2, %0;" : "+l"(d) : "l"(a), "l"(b));
}
__device__ __forceinline__ void fadd2(unsigned long long &d, unsigned long long a){
    asm("add.rn.f32x2 %0, %0, %1;" : "+l"(d) : "l"(a));
}
__device__ __forceinline__ float ulo(unsigned long long v){ return __uint_as_float((unsigned)v); }
__device__ __forceinline__ float uhi(unsigned long long v){ return __uint_as_float((unsigned)(v>>32)); }
__device__ __forceinline__ unsigned long long dup2(float m){
    unsigned long long r; unsigned mb = __float_as_uint(m);
    asm("mov.b64 %0, {%1, %1};" : "=l"(r) : "r"(mb));
    return r;
}

// ---------------- prepA: small composite mats + tables (round-12 version) ----------------
__global__ void __launch_bounds__(128) prepA_kernel(
    const float* __restrict__ Wfuse, const float* __restrict__ bfuse,
    const float* __restrict__ Wabs,  const float* __restrict__ babs,
    const float* __restrict__ Wfor,  const float* __restrict__ bfor,
    const float* __restrict__ EQd,   const float* __restrict__ EC,
    const float* __restrict__ EIT,   const float* __restrict__ EUT,
    const float* __restrict__ EHA)
{
    __shared__ float sh[D];
    const int tid = threadIdx.x;
    const int bid = blockIdx.x;

    if (bid < 468) {
        const float* vrow; const float* Wb; float* outp;
        if (bid < 128)      { vrow = Wfuse + bid*D;        Wb = Wabs;           outp = g_M1 + bid*D; }
        else if (bid < 256) { vrow = Wfuse + (bid-128)*D;  Wb = Wfor + 2*D*D;   outp = g_M2 + (bid-128)*D; }
        else if (bid < 356) { vrow = EUT + (bid-256)*D;    Wb = Wabs + D*D;     outp = g_UT + (bid-256)*D; }
        else if (bid < 368) { vrow = EHA + (bid-356)*D;    Wb = Wabs + 2*D*D;   outp = g_HA + (bid-356)*D; }
        else                { vrow = EIT + (bid-368)*D;    Wb = Wfor + D*D;     outp = g_IT + (bid-368)*D; }
        sh[tid] = vrow[tid];
        __syncthreads();
        float a0=0.f,a1=0.f,a2=0.f,a3=0.f,a4=0.f,a5=0.f,a6=0.f,a7=0.f;
        #pragma unroll
        for (int jj=0; jj<D; jj+=8){
            a0 += sh[jj+0]*Wb[(jj+0)*D+tid];
            a1 += sh[jj+1]*Wb[(jj+1)*D+tid];
            a2 += sh[jj+2]*Wb[(jj+2)*D+tid];
            a3 += sh[jj+3]*Wb[(jj+3)*D+tid];
            a4 += sh[jj+4]*Wb[(jj+4)*D+tid];
            a5 += sh[jj+5]*Wb[(jj+5)*D+tid];
            a6 += sh[jj+6]*Wb[(jj+6)*D+tid];
            a7 += sh[jj+7]*Wb[(jj+7)*D+tid];
        }
        outp[tid] = ((a0+a1)+(a2+a3))+((a4+a5)+(a6+a7));
    } else if (bid == 468) {
        float a0=0.f,a1=0.f,a2=0.f,a3=0.f;
        #pragma unroll
        for (int k=0;k<D;k+=4){
            a0 += Wfuse[(D+k+0)*D+tid]; a1 += Wfuse[(D+k+1)*D+tid];
            a2 += Wfuse[(D+k+2)*D+tid]; a3 += Wfuse[(D+k+3)*D+tid];
        }
        g_s1[tid]=(a0+a1)+(a2+a3);
    } else if (bid == 469) {
        sh[tid]=bfuse[tid]; __syncthreads();
        float a0=0.f,a1=0.f,a2=0.f,a3=0.f;
        #pragma unroll
        for (int k=0;k<D;k+=4){
            a0 += sh[k+0]*Wabs[(k+0)*D+tid]; a1 += sh[k+1]*Wabs[(k+1)*D+tid];
            a2 += sh[k+2]*Wabs[(k+2)*D+tid]; a3 += sh[k+3]*Wabs[(k+3)*D+tid];
        }
        g_bA[tid] = (a0+a1)+(a2+a3) + babs[tid];
    } else if (bid == 470) {
        sh[tid]=bfuse[tid]; __syncthreads();
        float a0=0.f,a1=0.f,a2=0.f,a3=0.f;
        #pragma unroll
        for (int k=0;k<D;k+=4){
            a0 += sh[k+0]*Wfor[(2*D+k+0)*D+tid]; a1 += sh[k+1]*Wfor[(2*D+k+1)*D+tid];
            a2 += sh[k+2]*Wfor[(2*D+k+2)*D+tid]; a3 += sh[k+3]*Wfor[(2*D+k+3)*D+tid];
        }
        g_bF[tid] = (a0+a1)+(a2+a3) + bfor[tid];
    } else if (bid < 475) {
        int c = (bid-471)*128 + tid;
        if (c < NC){
            float s=0.f;
            #pragma unroll
            for (int dd=0; dd<D; dd+=4){
                float4 e = *(const float4*)&EC[c*D+dd];
                s += e.x*e.x + e.y*e.y + e.z*e.z + e.w*e.w;
            }
            g_rnC[c] = 1.f/fmaxf(sqrtf(s), 1e-8f);
        }
    } else {
        int q = (bid-475)*128 + tid;
        if (q < NQ) g_qd[q] = 10.f/(1.f+__expf(-EQd[q]));
    }
}

// ---------------- prepB: 8-question tiles, f32x2-packed, balanced qdm ----------------
#define NBQ 139
#define QPB 72
#define SMEM_B ((2*D*D + 8*D) * (int)sizeof(float))

__global__ void __launch_bounds__(256) prepB_kernel(
    const float* __restrict__ EQ, const float* __restrict__ EC,
    const int* __restrict__ q2c, const int* __restrict__ q2cm,
    const float* __restrict__ Wabs, const float* __restrict__ Wfor)
{
    const int tid = threadIdx.x;
    const int bid = blockIdx.x;

    if (bid >= NBQ){                       // v1 / v2 blocks (need g_s1 from prepA)
        __shared__ float s1s[D];
        if (tid < D) s1s[tid] = g_s1[tid];
        __syncthreads();
        if (tid < D){
            const float* Wb = (bid==NBQ) ? Wabs : (Wfor + 2*D*D);
            float a0=0.f,a1=0.f,a2=0.f,a3=0.f;
            #pragma unroll
            for (int jj=0;jj<D;jj+=4){
                a0 += s1s[jj+0]*Wb[(jj+0)*D+tid]; a1 += s1s[jj+1]*Wb[(jj+1)*D+tid];
                a2 += s1s[jj+2]*Wb[(jj+2)*D+tid]; a3 += s1s[jj+3]*Wb[(jj+3)*D+tid];
            }
            float a = (a0+a1)+(a2+a3);
            if (bid==NBQ) g_v1[tid]=a; else g_v2[tid]=a;
        }
        return;
    }

    extern __shared__ float smem[];
    float* M1s = smem;            // D*D
    float* M2s = smem + D*D;      // D*D
    float* E8  = smem + 2*D*D;    // 8 questions interleaved: E8[jj*8+q]

    const int w    = tid>>5;      // warp 0..7 — qdm question slot
    const int lane = tid&31;
    const int eq   = tid&7;       // E-staging question slot
    const int eg   = tid>>3;      // E-staging jj group (0..31)

    for (int i=tid; i<D*D; i+=256){ M1s[i]=g_M1[i]; M2s[i]=g_M2[i]; }

    const int qbase = bid*QPB;

    float4 eR = make_float4(0.f,0.f,0.f,0.f);
    { int q = qbase+eq; if (q<NQ) eR = *(const float4*)&EQ[q*D + eg*4]; }
    int4 cidN = make_int4(0,0,0,0);
    float rn0N=0,rn1N=0,rn2N=0,rn3N=0,m0N=0,m1N=0,m2N=0,m3N=0;
    { int q = qbase+w;
      if (q<NQ){
        cidN = ((const int4*)q2c)[q];
        rn0N=g_rnC[cidN.x]; rn1N=g_rnC[cidN.y]; rn2N=g_rnC[cidN.z]; rn3N=g_rnC[cidN.w];
        int4 mm = ((const int4*)q2cm)[q];
        m0N=(float)mm.x; m1N=(float)mm.y; m2N=(float)mm.z; m3N=(float)mm.w;
      }
    }
    __syncthreads();   // M1s/M2s visible

    for (int tt=0; tt<9; tt++){
        const int qb = qbase + tt*8;
        {
            int jb = eg*4;
            E8[(jb+0)*8+eq]=eR.x; E8[(jb+1)*8+eq]=eR.y;
            E8[(jb+2)*8+eq]=eR.z; E8[(jb+3)*8+eq]=eR.w;
        }
        const int4  cidC = cidN;
        const float rn0C=rn0N, rn1C=rn1N, rn2C=rn2N, rn3C=rn3N;
        const float m0C=m0N, m1C=m1N, m2C=m2N, m3C=m3N;
        __syncthreads();

        if (tt<8){
            int q = qb+8+eq;
            eR = make_float4(0.f,0.f,0.f,0.f);
            if (q<NQ) eR = *(const float4*)&EQ[q*D + eg*4];
            int qm = qb+8+w;
            if (qm<NQ){
                cidN = ((const int4*)q2c)[qm];
                rn0N=g_rnC[cidN.x]; rn1N=g_rnC[cidN.y]; rn2N=g_rnC[cidN.z]; rn3N=g_rnC[cidN.w];
                int4 mm = ((const int4*)q2cm)[qm];
                m0N=(float)mm.x; m1N=(float)mm.y; m2N=(float)mm.z; m3N=(float)mm.w;
            }
        }

        const float* ec0 = EC + cidC.x*D + lane;
        const float* ec1 = EC + cidC.y*D + lane;
        const float* ec2 = EC + cidC.z*D + lane;
        const float* ec3 = EC + cidC.w*D + lane;
        float x00=ec0[0], x01=ec0[32], x02=ec0[64], x03=ec0[96];
        float x10=ec1[0], x11=ec1[32], x12=ec1[64], x13=ec1[96];
        float x20=ec2[0], x21=ec2[32], x22=ec2[64], x23=ec2[96];
        float x30=ec3[0], x31=ec3[32], x32=ec3[64], x33=ec3[96];

        {
            const int halfp = tid>>7, jj = tid&127;
            const float* Ms = halfp ? M2s : M1s;
            unsigned long long A0=0ull,A1=0ull,A2=0ull,A3=0ull;
            const ulonglong2* Ev = (const ulonglong2*)E8;
            #pragma unroll 8
            for (int jk=0; jk<D; jk++){
                ulonglong2 u0 = Ev[jk*2];
                ulonglong2 u1 = Ev[jk*2+1];
                unsigned long long mm = dup2(Ms[jk*D+jj]);
                ffma2(A0, u0.x, mm);
                ffma2(A1, u0.y, mm);
                ffma2(A2, u1.x, mm);
                ffma2(A3, u1.y, mm);
            }
            // interleaved store: g_P12[(q*D+jj)*2 + halfp]
            float* P = g_P12 + halfp;
            if (qb+0<NQ) P[((qb+0)*D+jj)*2]=ulo(A0);
            if (qb+1<NQ) P[((qb+1)*D+jj)*2]=uhi(A0);
            if (qb+2<NQ) P[((qb+2)*D+jj)*2]=ulo(A1);
            if (qb+3<NQ) P[((qb+3)*D+jj)*2]=uhi(A1);
            if (qb+4<NQ) P[((qb+4)*D+jj)*2]=ulo(A2);
            if (qb+5<NQ) P[((qb+5)*D+jj)*2]=uhi(A2);
            if (qb+6<NQ) P[((qb+6)*D+jj)*2]=ulo(A3);
            if (qb+7<NQ) P[((qb+7)*D+jj)*2]=uhi(A3);
        }

        if (qb+w < NQ){
            float e0=E8[(lane   )*8+w];
            float e1=E8[(lane+32)*8+w];
            float e2=E8[(lane+64)*8+w];
            float e3=E8[(lane+96)*8+w];
            float d0 = e0*x00 + e1*x01 + e2*x02 + e3*x03;
            float d1 = e0*x10 + e1*x11 + e2*x12 + e3*x13;
            float d2 = e0*x20 + e1*x21 + e2*x22 + e3*x23;
            float d3 = e0*x30 + e1*x31 + e2*x32 + e3*x33;
            float nrm = e0*e0+e1*e1+e2*e2+e3*e3;
            #pragma unroll
            for (int off=16; off; off>>=1){
                d0  += __shfl_down_sync(0xffffffffu, d0, off);
                d1  += __shfl_down_sync(0xffffffffu, d1, off);
                d2  += __shfl_down_sync(0xffffffffu, d2, off);
                d3  += __shfl_down_sync(0xffffffffu, d3, off);
                nrm += __shfl_down_sync(0xffffffffu, nrm, off);
            }
            if (lane==0){
                float rq = 1.f/fmaxf(sqrtf(nrm), 1e-8f);
                g_qdm[qb+w] = 0.5f*rq*(d0*rn0C*m0C + d1*rn1C*m1C + d2*rn2C*m2C + d3*rn3C*m3C)
                            + 0.5f*(m0C+m1C+m2C+m3C);
            }
        }
        __syncthreads();
    }
}

// ---------------- scan: round-12 structure + fused P12 load ----------------
#define SCAN_THREADS 192   // warps 0..3 matvec (1 column/thread), warps 4..5 output

#define MV_STEP(T, P1v,P2v,UTv,HAv,ITv, DO_BAR) do{                                      \
    float curP1_=P1v, curP2_=P2v, curUT_=UTv, curHA_=HAv, curIT_=ITv;                    \
    int tp_ = (T)+2; if (tp_ > S-1) tp_ = S-1;                                           \
    int qp_ = sq[tp_];                                                                   \
    float2 p12_ = __ldg((const float2*)&g_P12[(qp_*D+j)*2]);                             \
    P1v = p12_.x;                                                                        \
    P2v = p12_.y;                                                                        \
    UTv = __ldg(&g_UT[sut[tp_]*D+j]);                                                    \
    HAv = __ldg(&g_HA[sha[tp_]*D+j]);                                                    \
    ITv = __ldg(&g_IT[sit[tp_]*D+j]);                                                    \
    float ctv_   = (float)sc[T];                                                         \
    float basea_ = curP1_ + ctv_*rv1 + curUT_ + curHA_ + rbA;                            \
    float basez_ = curP2_ + ctv_*rv2 + curIT_ + rbF;                                     \
    const float* lprev_ = lring[((T)+3)&3];                                              \
    float lpj_ = lprev_[j];                                                              \
    const ulonglong2* xp_ = (const ulonglong2*)lprev_;                                   \
    unsigned long long a0_=0ull,a1_=0ull,a2_=0ull,a3_=0ull;                              \
    _Pragma("unroll")                                                                    \
    for (int i_=0; i_<32; i_+=2){                                                        \
        ulonglong2 v0_ = xp_[i_];                                                        \
        ulonglong2 v1_ = xp_[i_+1];                                                      \
        ffma2(a0_, v0_.x, w2[2*i_  ]);                                                   \
        ffma2(a1_, v0_.y, w2[2*i_+1]);                                                   \
        ffma2(a2_, v1_.x, w2[2*i_+2]);                                                   \
        ffma2(a3_, v1_.y, w2[2*i_+3]);                                                   \
    }                                                                                    \
    fadd2(a0_,a1_); fadd2(a2_,a3_); fadd2(a0_,a2_);                                      \
    float z_ = (ulo(a0_) + uhi(a0_)) + basez_;                                           \
    float f_ = 1.f/(1.f+__expf(-z_));                                                    \
    lring[(T)&3][j] = lpj_*f_ + basea_;                                                  \
    if (DO_BAR) asm volatile("bar.sync 1, 128;" ::: "memory");                           \
}while(0)

#define OW_LOAD_SET(SFX, o) do{                                                          \
    int q1_ = sq[(o)+1];                                                                 \
    int4 cid_ = __ldg((const int4*)q2c + q1_);                                           \
    const float* e0_ = EC + cid_.x*D + lane;                                             \
    const float* e1_ = EC + cid_.y*D + lane;                                             \
    const float* e2_ = EC + cid_.z*D + lane;                                             \
    const float* e3_ = EC + cid_.w*D + lane;                                             \
    E##SFX[0]=e0_[0];  E##SFX[1]=e0_[32];  E##SFX[2]=e0_[64];  E##SFX[3]=e0_[96];        \
    E##SFX[4]=e1_[0];  E##SFX[5]=e1_[32];  E##SFX[6]=e1_[64];  E##SFX[7]=e1_[96];        \
    E##SFX[8]=e2_[0];  E##SFX[9]=e2_[32];  E##SFX[10]=e2_[64]; E##SFX[11]=e2_[96];       \
    E##SFX[12]=e3_[0]; E##SFX[13]=e3_[32]; E##SFX[14]=e3_[64]; E##SFX[15]=e3_[96];       \
    if (lane==0){                                                                        \
        rn0##SFX=g_rnC[cid_.x]; rn1##SFX=g_rnC[cid_.y];                                  \
        rn2##SFX=g_rnC[cid_.z]; rn3##SFX=g_rnC[cid_.w];                                  \
        qd##SFX=g_qd[q1_];                                                               \
        int qt_ = sq[o]; qdm##SFX=g_qdm[qt_];                                            \
        int4 mm_ = __ldg((const int4*)q2cm + qt_);                                       \
        m0##SFX=(float)mm_.x; m1##SFX=(float)mm_.y;                                      \
        m2##SFX=(float)mm_.z; m3##SFX=(float)mm_.w;                                      \
    }                                                                                    \
}while(0)

#define OW_EMIT_SET(SFX, o) do{                                                          \
    const float* lcv_ = lring[(o)&3];                                                    \
    float x0_=lcv_[lane], x1_=lcv_[lane+32], x2_=lcv_[lane+64], x3_=lcv_[lane+96];       \
    float d0_ = x0_*E##SFX[0]  + x1_*E##SFX[1]  + x2_*E##SFX[2]  + x3_*E##SFX[3];        \
    float d1_ = x0_*E##SFX[4]  + x1_*E##SFX[5]  + x2_*E##SFX[6]  + x3_*E##SFX[7];        \
    float d2_ = x0_*E##SFX[8]  + x1_*E##SFX[9]  + x2_*E##SFX[10] + x3_*E##SFX[11];       \
    float d3_ = x0_*E##SFX[12] + x1_*E##SFX[13] + x2_*E##SFX[14] + x3_*E##SFX[15];       \
    float nv_ = x0_*x0_ + x1_*x1_ + x2_*x2_ + x3_*x3_;                                   \
    _Pragma("unroll")                                                                    \
    for (int o_=16;o_;o_>>=1){                                                           \
        d0_ += __shfl_down_sync(0xffffffffu, d0_, o_);                                   \
        d1_ += __shfl_down_sync(0xffffffffu, d1_, o_);                                   \
        d2_ += __shfl_down_sync(0xffffffffu, d2_, o_);                                   \
        d3_ += __shfl_down_sync(0xffffffffu, d3_, o_);                                   \
        nv_ += __shfl_down_sync(0xffffffffu, nv_, o_);                                   \
    }                                                                                    \
    if (lane==0){                                                                        \
        float rl_ = 1.f/fmaxf(sqrtf(nv_), 1e-8f);                                        \
        float ss_ = 0.5f*((d0_*rn0##SFX*rl_+1.f)*m0##SFX + (d1_*rn1##SFX*rl_+1.f)*m1##SFX\
                        + (d2_*rn2##SFX*rl_+1.f)*m2##SFX + (d3_*rn3##SFX*rl_+1.f)*m3##SFX);\
        float lg_ = qd##SFX*(ss_ - qdm##SFX);                                            \
        out[b*S+(o)] = 1.f/(1.f+__expf(-lg_));                                           \
    }                                                                                    \
}while(0)

#define OW_EVEN(T) do{                                                                   \
    int o_ = (T) + p;                                                                    \
    if (o_ <= S-2){                                                                      \
        if ((((T)>>1)&1)==0) OW_LOAD_SET(A, o_);                                         \
        else                 OW_LOAD_SET(B, o_);                                         \
    }                                                                                    \
}while(0)

#define OW_ODD(T) do{                                                                    \
    if ((T) >= 3){                                                                       \
        int o_ = (T)-3+p;                                                                \
        if (((((T)-3)>>1)&1)==0) OW_EMIT_SET(A, o_);                                     \
        else                     OW_EMIT_SET(B, o_);                                     \
    }                                                                                    \
}while(0)

__global__ void __launch_bounds__(SCAN_THREADS,1) scan_kernel(
    const int* __restrict__ qseq, const int* __restrict__ haseq,
    const int* __restrict__ cseq, const int* __restrict__ itseq,
    const int* __restrict__ utseq,
    const int* __restrict__ q2c, const int* __restrict__ q2cm,
    const float* __restrict__ EC, const float* __restrict__ Wfor,
    const float* __restrict__ lat0, float* __restrict__ out)
{
    __shared__ __align__(16) float lring[4][D];   // slot t&3 = lc_t; slot 3 init = latent0
    __shared__ int sq[S], sha[S], sc[S], sit[S], sut[S];

    const int b    = blockIdx.x;
    const int tid  = threadIdx.x;
    const int lane = tid & 31;
    const bool ow  = (tid >= 128);
    const int j    = tid;               // matvec column (only valid when !ow)
    const int p    = (tid>>5) - 4;      // output warp parity (0/1)

    for (int i=tid; i<S; i+=SCAN_THREADS){
        sq[i]=qseq[b*S+i]; sha[i]=haseq[b*S+i]; sc[i]=cseq[b*S+i];
        sit[i]=itseq[b*S+i]; sut[i]=utseq[b*S+i];
    }
    if (tid < D) lring[3][tid] = lat0[b*D+tid];

    unsigned long long w2[64];
    float rv1=0.f, rv2=0.f, rbA=0.f, rbF=0.f;
    if (!ow){
        #pragma unroll
        for (int kk=0; kk<64; kk++){
            unsigned lo = __float_as_uint(Wfor[(2*kk  )*D + j]);
            unsigned hi = __float_as_uint(Wfor[(2*kk+1)*D + j]);
            w2[kk] = ((unsigned long long)hi << 32) | lo;
        }
        rv1=g_v1[j]; rv2=g_v2[j]; rbA=g_bA[j]; rbF=g_bF[j];
    }
    __syncthreads();   // seqs + lring[3] visible

    // depth-2 prefetch: set A = even steps, set B = odd steps
    float pA1=0,pA2=0,pA3=0,pA4=0,pA5=0;
    float pB1=0,pB2=0,pB3=0,pB4=0,pB5=0;
    if (!ow){
        int q0 = sq[0];
        float2 p0 = __ldg((const float2*)&g_P12[(q0*D+j)*2]);
        pA1 = p0.x; pA2 = p0.y;
        pA3 = g_UT[sut[0]*D+j]; pA4 = g_HA[sha[0]*D+j]; pA5 = g_IT[sit[0]*D+j];
        int q1 = sq[1];
        float2 p1 = __ldg((const float2*)&g_P12[(q1*D+j)*2]);
        pB1 = p1.x; pB2 = p1.y;
        pB3 = g_UT[sut[1]*D+j]; pB4 = g_HA[sha[1]*D+j]; pB5 = g_IT[sit[1]*D+j];
    }

    float EA[16], EB[16];
    float rn0A=0,rn1A=0,rn2A=0,rn3A=0,qdA=0,qdmA=0,m0A=0,m1A=0,m2A=0,m3A=0;
    float rn0B=0,rn1B=0,rn2B=0,rn3B=0,qdB=0,qdmB=0,m0B=0,m1B=0,m2B=0,m3B=0;

    for (int t=0; t<S-2; t+=2){
        if (!ow) MV_STEP(t,   pA1,pA2,pA3,pA4,pA5, 1);
        else     OW_EVEN(t);
        if (!ow) MV_STEP(t+1, pB1,pB2,pB3,pB4,pB5, 0);
        else     OW_ODD(t+1);
        __syncthreads();
    }
    if (!ow) MV_STEP(S-2, pA1,pA2,pA3,pA4,pA5, 0);
    else     OW_EVEN(S-2);
    __syncthreads();

    if (ow){
        { int o = 196 + p; OW_EMIT_SET(A, o); }
        if (p == 0){ OW_EMIT_SET(B, 198); }
    }
    if (tid==0) out[b*S + (S-1)] = 0.f;
}

extern "C" void kernel_launch(void* const* d_in, const int* in_sizes, int n_in,
                              void* d_out, int out_size)
{
    const int*   qseq  = (const int*)  d_in[0];
    const int*   haseq = (const int*)  d_in[1];
    const int*   cseq  = (const int*)  d_in[2];
    const int*   itseq = (const int*)  d_in[3];
    const int*   utseq = (const int*)  d_in[4];
    const int*   q2c   = (const int*)  d_in[5];
    const int*   q2cm  = (const int*)  d_in[6];
    const float* EQ    = (const float*)d_in[7];
    const float* EQd   = (const float*)d_in[8];
    const float* EC    = (const float*)d_in[9];
    const float* EIT   = (const float*)d_in[10];
    const float* EUT   = (const float*)d_in[11];
    const float* EHA   = (const float*)d_in[12];
    const float* Wfuse = (const float*)d_in[13];
    const float* bfuse = (const float*)d_in[14];
    const float* Wabs  = (const float*)d_in[15];
    const float* babs  = (const float*)d_in[16];
    const float* Wfor  = (const float*)d_in[17];
    const float* bfor  = (const float*)d_in[18];
    const float* lat0  = (const float*)d_in[19];
    float* out = (float*)d_out;

    cudaFuncSetAttribute(prepB_kernel,
                         cudaFuncAttributeMaxDynamicSharedMemorySize, SMEM_B);

    prepA_kernel<<<554, 128>>>(Wfuse, bfuse, Wabs, babs, Wfor, bfor,
                               EQd, EC, EIT, EUT, EHA);
    prepB_kernel<<<NBQ+2, 256, SMEM_B>>>(EQ, EC, q2c, q2cm, Wabs, Wfor);
    scan_kernel<<<B, SCAN_THREADS>>>(qseq, haseq, cseq, itseq, utseq,
                                     q2c, q2cm, EC, Wfor, lat0, out);
}

// round 17
// speedup vs baseline: 1.6371x; 1.1736x over previous
#include <cuda_runtime.h>
#include <math.h>

#define D   128
#define B   128
#define S   200
#define NQ  10000
#define NC  500

// ---------------- scratch tables (device globals; no allocation) ----------------
__device__ float g_M1[D*D];      // W_fuse_top @ W_absorb_top
__device__ float g_M2[D*D];      // W_fuse_top @ W_forget_bot
__device__ float g_UT[100*D];    // embed_use_time @ W_absorb_mid
__device__ float g_HA[12*D];     // embed_hint_attempt @ W_absorb_bot
__device__ float g_IT[100*D];    // embed_interval_time @ W_forget_mid
__device__ float g_s1[D];        // colsum(W_fuse_bot)
__device__ float g_v1[D];        // s1 @ W_absorb_top
__device__ float g_v2[D];        // s1 @ W_forget_bot
__device__ float g_bA[D];        // b_fuse @ W_absorb_top + b_absorb
__device__ float g_bF[D];        // b_fuse @ W_forget_bot + b_forget
__device__ float g_P12[NQ*D*2];  // interleaved: [q][j][0]=P1, [q][j][1]=P2
__device__ float g_qd[NQ];       // 10*sigmoid(disc)
__device__ float g_qdm[NQ];      // sum_k qdiff_k * mask_k  (per question)
__device__ float g_rnC[NC];      // 1/max(|concept|,eps)
__device__ float g_LC[B*S*D];    // lc_t vectors from the scan (read by post kernel)

// packed f32x2 ops (sm_100+)
__device__ __forceinline__ void ffma2(unsigned long long &d,
                                      unsigned long long a, unsigned long long b){
    asm("fma.rn.f32x2 %0, %1, %2, %0;" : "+l"(d) : "l"(a), "l"(b));
}
__device__ __forceinline__ void fadd2(unsigned long long &d, unsigned long long a){
    asm("add.rn.f32x2 %0, %0, %1;" : "+l"(d) : "l"(a));
}
__device__ __forceinline__ float ulo(unsigned long long v){ return __uint_as_float((unsigned)v); }
__device__ __forceinline__ float uhi(unsigned long long v){ return __uint_as_float((unsigned)(v>>32)); }
__device__ __forceinline__ unsigned long long dup2(float m){
    unsigned long long r; unsigned mb = __float_as_uint(m);
    asm("mov.b64 %0, {%1, %1};" : "=l"(r) : "r"(mb));
    return r;
}

// ---------------- prepA: small composite mats + tables (round-12 version) ----------------
__global__ void __launch_bounds__(128) prepA_kernel(
    const float* __restrict__ Wfuse, const float* __restrict__ bfuse,
    const float* __restrict__ Wabs,  const float* __restrict__ babs,
    const float* __restrict__ Wfor,  const float* __restrict__ bfor,
    const float* __restrict__ EQd,   const float* __restrict__ EC,
    const float* __restrict__ EIT,   const float* __restrict__ EUT,
    const float* __restrict__ EHA)
{
    __shared__ float sh[D];
    const int tid = threadIdx.x;
    const int bid = blockIdx.x;

    if (bid < 468) {
        const float* vrow; const float* Wb; float* outp;
        if (bid < 128)      { vrow = Wfuse + bid*D;        Wb = Wabs;           outp = g_M1 + bid*D; }
        else if (bid < 256) { vrow = Wfuse + (bid-128)*D;  Wb = Wfor + 2*D*D;   outp = g_M2 + (bid-128)*D; }
        else if (bid < 356) { vrow = EUT + (bid-256)*D;    Wb = Wabs + D*D;     outp = g_UT + (bid-256)*D; }
        else if (bid < 368) { vrow = EHA + (bid-356)*D;    Wb = Wabs + 2*D*D;   outp = g_HA + (bid-356)*D; }
        else                { vrow = EIT + (bid-368)*D;    Wb = Wfor + D*D;     outp = g_IT + (bid-368)*D; }
        sh[tid] = vrow[tid];
        __syncthreads();
        float a0=0.f,a1=0.f,a2=0.f,a3=0.f,a4=0.f,a5=0.f,a6=0.f,a7=0.f;
        #pragma unroll
        for (int jj=0; jj<D; jj+=8){
            a0 += sh[jj+0]*Wb[(jj+0)*D+tid];
            a1 += sh[jj+1]*Wb[(jj+1)*D+tid];
            a2 += sh[jj+2]*Wb[(jj+2)*D+tid];
            a3 += sh[jj+3]*Wb[(jj+3)*D+tid];
            a4 += sh[jj+4]*Wb[(jj+4)*D+tid];
            a5 += sh[jj+5]*Wb[(jj+5)*D+tid];
            a6 += sh[jj+6]*Wb[(jj+6)*D+tid];
            a7 += sh[jj+7]*Wb[(jj+7)*D+tid];
        }
        outp[tid] = ((a0+a1)+(a2+a3))+((a4+a5)+(a6+a7));
    } else if (bid == 468) {
        float a0=0.f,a1=0.f,a2=0.f,a3=0.f;
        #pragma unroll
        for (int k=0;k<D;k+=4){
            a0 += Wfuse[(D+k+0)*D+tid]; a1 += Wfuse[(D+k+1)*D+tid];
            a2 += Wfuse[(D+k+2)*D+tid]; a3 += Wfuse[(D+k+3)*D+tid];
        }
        g_s1[tid]=(a0+a1)+(a2+a3);
    } else if (bid == 469) {
        sh[tid]=bfuse[tid]; __syncthreads();
        float a0=0.f,a1=0.f,a2=0.f,a3=0.f;
        #pragma unroll
        for (int k=0;k<D;k+=4){
            a0 += sh[k+0]*Wabs[(k+0)*D+tid]; a1 += sh[k+1]*Wabs[(k+1)*D+tid];
            a2 += sh[k+2]*Wabs[(k+2)*D+tid]; a3 += sh[k+3]*Wabs[(k+3)*D+tid];
        }
        g_bA[tid] = (a0+a1)+(a2+a3) + babs[tid];
    } else if (bid == 470) {
        sh[tid]=bfuse[tid]; __syncthreads();
        float a0=0.f,a1=0.f,a2=0.f,a3=0.f;
        #pragma unroll
        for (int k=0;k<D;k+=4){
            a0 += sh[k+0]*Wfor[(2*D+k+0)*D+tid]; a1 += sh[k+1]*Wfor[(2*D+k+1)*D+tid];
            a2 += sh[k+2]*Wfor[(2*D+k+2)*D+tid]; a3 += sh[k+3]*Wfor[(2*D+k+3)*D+tid];
        }
        g_bF[tid] = (a0+a1)+(a2+a3) + bfor[tid];
    } else if (bid < 475) {
        int c = (bid-471)*128 + tid;
        if (c < NC){
            float s=0.f;
            #pragma unroll
            for (int dd=0; dd<D; dd+=4){
                float4 e = *(const float4*)&EC[c*D+dd];
                s += e.x*e.x + e.y*e.y + e.z*e.z + e.w*e.w;
            }
            g_rnC[c] = 1.f/fmaxf(sqrtf(s), 1e-8f);
        }
    } else {
        int q = (bid-475)*128 + tid;
        if (q < NQ) g_qd[q] = 10.f/(1.f+__expf(-EQd[q]));
    }
}

// ---------------- prepB: 8-question tiles, f32x2-packed, balanced qdm ----------------
#define NBQ 139
#define QPB 72
#define SMEM_B ((2*D*D + 8*D) * (int)sizeof(float))

__global__ void __launch_bounds__(256) prepB_kernel(
    const float* __restrict__ EQ, const float* __restrict__ EC,
    const int* __restrict__ q2c, const int* __restrict__ q2cm,
    const float* __restrict__ Wabs, const float* __restrict__ Wfor)
{
    const int tid = threadIdx.x;
    const int bid = blockIdx.x;

    if (bid >= NBQ){                       // v1 / v2 blocks (need g_s1 from prepA)
        __shared__ float s1s[D];
        if (tid < D) s1s[tid] = g_s1[tid];
        __syncthreads();
        if (tid < D){
            const float* Wb = (bid==NBQ) ? Wabs : (Wfor + 2*D*D);
            float a0=0.f,a1=0.f,a2=0.f,a3=0.f;
            #pragma unroll
            for (int jj=0;jj<D;jj+=4){
                a0 += s1s[jj+0]*Wb[(jj+0)*D+tid]; a1 += s1s[jj+1]*Wb[(jj+1)*D+tid];
                a2 += s1s[jj+2]*Wb[(jj+2)*D+tid]; a3 += s1s[jj+3]*Wb[(jj+3)*D+tid];
            }
            float a = (a0+a1)+(a2+a3);
            if (bid==NBQ) g_v1[tid]=a; else g_v2[tid]=a;
        }
        return;
    }

    extern __shared__ float smem[];
    float* M1s = smem;            // D*D
    float* M2s = smem + D*D;      // D*D
    float* E8  = smem + 2*D*D;    // 8 questions interleaved: E8[jj*8+q]

    const int w    = tid>>5;      // warp 0..7 — qdm question slot
    const int lane = tid&31;
    const int eq   = tid&7;       // E-staging question slot
    const int eg   = tid>>3;      // E-staging jj group (0..31)

    for (int i=tid; i<D*D; i+=256){ M1s[i]=g_M1[i]; M2s[i]=g_M2[i]; }

    const int qbase = bid*QPB;

    float4 eR = make_float4(0.f,0.f,0.f,0.f);
    { int q = qbase+eq; if (q<NQ) eR = *(const float4*)&EQ[q*D + eg*4]; }
    int4 cidN = make_int4(0,0,0,0);
    float rn0N=0,rn1N=0,rn2N=0,rn3N=0,m0N=0,m1N=0,m2N=0,m3N=0;
    { int q = qbase+w;
      if (q<NQ){
        cidN = ((const int4*)q2c)[q];
        rn0N=g_rnC[cidN.x]; rn1N=g_rnC[cidN.y]; rn2N=g_rnC[cidN.z]; rn3N=g_rnC[cidN.w];
        int4 mm = ((const int4*)q2cm)[q];
        m0N=(float)mm.x; m1N=(float)mm.y; m2N=(float)mm.z; m3N=(float)mm.w;
      }
    }
    __syncthreads();   // M1s/M2s visible

    for (int tt=0; tt<9; tt++){
        const int qb = qbase + tt*8;
        {
            int jb = eg*4;
            E8[(jb+0)*8+eq]=eR.x; E8[(jb+1)*8+eq]=eR.y;
            E8[(jb+2)*8+eq]=eR.z; E8[(jb+3)*8+eq]=eR.w;
        }
        const int4  cidC = cidN;
        const float rn0C=rn0N, rn1C=rn1N, rn2C=rn2N, rn3C=rn3N;
        const float m0C=m0N, m1C=m1N, m2C=m2N, m3C=m3N;
        __syncthreads();

        if (tt<8){
            int q = qb+8+eq;
            eR = make_float4(0.f,0.f,0.f,0.f);
            if (q<NQ) eR = *(const float4*)&EQ[q*D + eg*4];
            int qm = qb+8+w;
            if (qm<NQ){
                cidN = ((const int4*)q2c)[qm];
                rn0N=g_rnC[cidN.x]; rn1N=g_rnC[cidN.y]; rn2N=g_rnC[cidN.z]; rn3N=g_rnC[cidN.w];
                int4 mm = ((const int4*)q2cm)[qm];
                m0N=(float)mm.x; m1N=(float)mm.y; m2N=(float)mm.z; m3N=(float)mm.w;
            }
        }

        const float* ec0 = EC + cidC.x*D + lane;
        const float* ec1 = EC + cidC.y*D + lane;
        const float* ec2 = EC + cidC.z*D + lane;
        const float* ec3 = EC + cidC.w*D + lane;
        float x00=ec0[0], x01=ec0[32], x02=ec0[64], x03=ec0[96];
        float x10=ec1[0], x11=ec1[32], x12=ec1[64], x13=ec1[96];
        float x20=ec2[0], x21=ec2[32], x22=ec2[64], x23=ec2[96];
        float x30=ec3[0], x31=ec3[32], x32=ec3[64], x33=ec3[96];

        {
            const int halfp = tid>>7, jj = tid&127;
            const float* Ms = halfp ? M2s : M1s;
            unsigned long long A0=0ull,A1=0ull,A2=0ull,A3=0ull;
            const ulonglong2* Ev = (const ulonglong2*)E8;
            #pragma unroll 8
            for (int jk=0; jk<D; jk++){
                ulonglong2 u0 = Ev[jk*2];
                ulonglong2 u1 = Ev[jk*2+1];
                unsigned long long mm = dup2(Ms[jk*D+jj]);
                ffma2(A0, u0.x, mm);
                ffma2(A1, u0.y, mm);
                ffma2(A2, u1.x, mm);
                ffma2(A3, u1.y, mm);
            }
            float* P = g_P12 + halfp;
            if (qb+0<NQ) P[((qb+0)*D+jj)*2]=ulo(A0);
            if (qb+1<NQ) P[((qb+1)*D+jj)*2]=uhi(A0);
            if (qb+2<NQ) P[((qb+2)*D+jj)*2]=ulo(A1);
            if (qb+3<NQ) P[((qb+3)*D+jj)*2]=uhi(A1);
            if (qb+4<NQ) P[((qb+4)*D+jj)*2]=ulo(A2);
            if (qb+5<NQ) P[((qb+5)*D+jj)*2]=uhi(A2);
            if (qb+6<NQ) P[((qb+6)*D+jj)*2]=ulo(A3);
            if (qb+7<NQ) P[((qb+7)*D+jj)*2]=uhi(A3);
        }

        if (qb+w < NQ){
            float e0=E8[(lane   )*8+w];
            float e1=E8[(lane+32)*8+w];
            float e2=E8[(lane+64)*8+w];
            float e3=E8[(lane+96)*8+w];
            float d0 = e0*x00 + e1*x01 + e2*x02 + e3*x03;
            float d1 = e0*x10 + e1*x11 + e2*x12 + e3*x13;
            float d2 = e0*x20 + e1*x21 + e2*x22 + e3*x23;
            float d3 = e0*x30 + e1*x31 + e2*x32 + e3*x33;
            float nrm = e0*e0+e1*e1+e2*e2+e3*e3;
            #pragma unroll
            for (int off=16; off; off>>=1){
                d0  += __shfl_down_sync(0xffffffffu, d0, off);
                d1  += __shfl_down_sync(0xffffffffu, d1, off);
                d2  += __shfl_down_sync(0xffffffffu, d2, off);
                d3  += __shfl_down_sync(0xffffffffu, d3, off);
                nrm += __shfl_down_sync(0xffffffffu, nrm, off);
            }
            if (lane==0){
                float rq = 1.f/fmaxf(sqrtf(nrm), 1e-8f);
                g_qdm[qb+w] = 0.5f*rq*(d0*rn0C*m0C + d1*rn1C*m1C + d2*rn2C*m2C + d3*rn3C*m3C)
                            + 0.5f*(m0C+m1C+m2C+m3C);
            }
        }
        __syncthreads();
    }
}

// ---------------- scan: 4 symmetric matvec warps only; lc streamed to global ----------------
#define SCAN_THREADS 128

#define MV_STEP(T, P1v,P2v,UTv,HAv,ITv) do{                                              \
    float curP1_=P1v, curP2_=P2v, curUT_=UTv, curHA_=HAv, curIT_=ITv;                    \
    int tp_ = (T)+2; if (tp_ > S-1) tp_ = S-1;                                           \
    int qp_ = sq[tp_];                                                                   \
    float2 p12_ = __ldg((const float2*)&g_P12[(qp_*D+j)*2]);                             \
    P1v = p12_.x;                                                                        \
    P2v = p12_.y;                                                                        \
    UTv = __ldg(&g_UT[sut[tp_]*D+j]);                                                    \
    HAv = __ldg(&g_HA[sha[tp_]*D+j]);                                                    \
    ITv = __ldg(&g_IT[sit[tp_]*D+j]);                                                    \
    float ctv_   = (float)sc[T];                                                         \
    float basea_ = curP1_ + ctv_*rv1 + curUT_ + curHA_ + rbA;                            \
    float basez_ = curP2_ + ctv_*rv2 + curIT_ + rbF;                                     \
    const float* lprev_ = lring[((T)+3)&3];                                              \
    float lpj_ = lprev_[j];                                                              \
    const ulonglong2* xp_ = (const ulonglong2*)lprev_;                                   \
    unsigned long long a0_=0ull,a1_=0ull,a2_=0ull,a3_=0ull;                              \
    _Pragma("unroll")                                                                    \
    for (int i_=0; i_<32; i_+=2){                                                        \
        ulonglong2 v0_ = xp_[i_];                                                        \
        ulonglong2 v1_ = xp_[i_+1];                                                      \
        ffma2(a0_, v0_.x, w2[2*i_  ]);                                                   \
        ffma2(a1_, v0_.y, w2[2*i_+1]);                                                   \
        ffma2(a2_, v1_.x, w2[2*i_+2]);                                                   \
        ffma2(a3_, v1_.y, w2[2*i_+3]);                                                   \
    }                                                                                    \
    fadd2(a0_,a1_); fadd2(a2_,a3_); fadd2(a0_,a2_);                                      \
    float z_ = (ulo(a0_) + uhi(a0_)) + basez_;                                           \
    float f_ = 1.f/(1.f+__expf(-z_));                                                    \
    float lc_ = lpj_*f_ + basea_;                                                        \
    lring[(T)&3][j] = lc_;                                                               \
    g_LC[(bS+(T))*D + j] = lc_;                                                          \
    __syncthreads();                                                                     \
}while(0)

__global__ void __launch_bounds__(SCAN_THREADS,1) scan_kernel(
    const int* __restrict__ qseq, const int* __restrict__ haseq,
    const int* __restrict__ cseq, const int* __restrict__ itseq,
    const int* __restrict__ utseq,
    const float* __restrict__ Wfor,
    const float* __restrict__ lat0, float* __restrict__ out)
{
    __shared__ __align__(16) float lring[4][D];   // slot t&3 = lc_t; slot 3 init = latent0
    __shared__ int sq[S], sha[S], sc[S], sit[S], sut[S];

    const int b   = blockIdx.x;
    const int tid = threadIdx.x;
    const int j   = tid;
    const int bS  = b*S;

    for (int i=tid; i<S; i+=SCAN_THREADS){
        sq[i]=qseq[bS+i]; sha[i]=haseq[bS+i]; sc[i]=cseq[bS+i];
        sit[i]=itseq[bS+i]; sut[i]=utseq[bS+i];
    }
    lring[3][tid] = lat0[b*D+tid];

    unsigned long long w2[64];
    #pragma unroll
    for (int kk=0; kk<64; kk++){
        unsigned lo = __float_as_uint(Wfor[(2*kk  )*D + j]);
        unsigned hi = __float_as_uint(Wfor[(2*kk+1)*D + j]);
        w2[kk] = ((unsigned long long)hi << 32) | lo;
    }
    float rv1=g_v1[j], rv2=g_v2[j], rbA=g_bA[j], rbF=g_bF[j];
    __syncthreads();   // seqs + lring[3] visible

    // depth-2 prefetch: set A = even steps, set B = odd steps
    float pA1,pA2,pA3,pA4,pA5, pB1,pB2,pB3,pB4,pB5;
    {
        int q0 = sq[0];
        float2 p0 = __ldg((const float2*)&g_P12[(q0*D+j)*2]);
        pA1 = p0.x; pA2 = p0.y;
        pA3 = g_UT[sut[0]*D+j]; pA4 = g_HA[sha[0]*D+j]; pA5 = g_IT[sit[0]*D+j];
        int q1 = sq[1];
        float2 p1 = __ldg((const float2*)&g_P12[(q1*D+j)*2]);
        pB1 = p1.x; pB2 = p1.y;
        pB3 = g_UT[sut[1]*D+j]; pB4 = g_HA[sha[1]*D+j]; pB5 = g_IT[sit[1]*D+j];
    }

    for (int t=0; t<S-2; t+=2){
        MV_STEP(t,   pA1,pA2,pA3,pA4,pA5);
        MV_STEP(t+1, pB1,pB2,pB3,pB4,pB5);
    }
    MV_STEP(S-2, pA1,pA2,pA3,pA4,pA5);
    if (tid==0) out[bS + (S-1)] = 0.f;
}

// ---------------- post: one warp per output; reads g_LC ----------------
#define POST_THREADS 256
#define POST_WPB (POST_THREADS/32)
#define NOUT (B*(S-1))

__global__ void __launch_bounds__(POST_THREADS) post_kernel(
    const int* __restrict__ qseq,
    const int* __restrict__ q2c, const int* __restrict__ q2cm,
    const float* __restrict__ EC, float* __restrict__ out)
{
    const int gw   = blockIdx.x*POST_WPB + (threadIdx.x>>5);
    const int lane = threadIdx.x & 31;
    if (gw >= NOUT) return;
    const int b = gw / (S-1);
    const int o = gw - b*(S-1);

    const int qt = qseq[b*S+o];
    const int q1 = qseq[b*S+o+1];
    int4 cid = __ldg((const int4*)q2c + q1);

    const float* lc = g_LC + (b*S+o)*D;
    float x0=lc[lane], x1=lc[lane+32], x2=lc[lane+64], x3=lc[lane+96];

    const float* e0_ = EC + cid.x*D + lane;
    const float* e1_ = EC + cid.y*D + lane;
    const float* e2_ = EC + cid.z*D + lane;
    const float* e3_ = EC + cid.w*D + lane;
    float d0 = x0*e0_[0] + x1*e0_[32] + x2*e0_[64] + x3*e0_[96];
    float d1 = x0*e1_[0] + x1*e1_[32] + x2*e1_[64] + x3*e1_[96];
    float d2 = x0*e2_[0] + x1*e2_[32] + x2*e2_[64] + x3*e2_[96];
    float d3 = x0*e3_[0] + x1*e3_[32] + x2*e3_[64] + x3*e3_[96];
    float nv = x0*x0 + x1*x1 + x2*x2 + x3*x3;
    #pragma unroll
    for (int off=16; off; off>>=1){
        d0 += __shfl_down_sync(0xffffffffu, d0, off);
        d1 += __shfl_down_sync(0xffffffffu, d1, off);
        d2 += __shfl_down_sync(0xffffffffu, d2, off);
        d3 += __shfl_down_sync(0xffffffffu, d3, off);
        nv += __shfl_down_sync(0xffffffffu, nv, off);
    }
    if (lane==0){
        float rl = 1.f/fmaxf(sqrtf(nv), 1e-8f);
        int4 mm = __ldg((const int4*)q2cm + qt);
        float ss = 0.5f*((d0*g_rnC[cid.x]*rl+1.f)*(float)mm.x
                       + (d1*g_rnC[cid.y]*rl+1.f)*(float)mm.y
                       + (d2*g_rnC[cid.z]*rl+1.f)*(float)mm.z
                       + (d3*g_rnC[cid.w]*rl+1.f)*(float)mm.w);
        float lg = g_qd[q1]*(ss - g_qdm[qt]);
        out[b*S+o] = 1.f/(1.f+__expf(-lg));
    }
}

extern "C" void kernel_launch(void* const* d_in, const int* in_sizes, int n_in,
                              void* d_out, int out_size)
{
    const int*   qseq  = (const int*)  d_in[0];
    const int*   haseq = (const int*)  d_in[1];
    const int*   cseq  = (const int*)  d_in[2];
    const int*   itseq = (const int*)  d_in[3];
    const int*   utseq = (const int*)  d_in[4];
    const int*   q2c   = (const int*)  d_in[5];
    const int*   q2cm  = (const int*)  d_in[6];
    const float* EQ    = (const float*)d_in[7];
    const float* EQd   = (const float*)d_in[8];
    const float* EC    = (const float*)d_in[9];
    const float* EIT   = (const float*)d_in[10];
    const float* EUT   = (const float*)d_in[11];
    const float* EHA   = (const float*)d_in[12];
    const float* Wfuse = (const float*)d_in[13];
    const float* bfuse = (const float*)d_in[14];
    const float* Wabs  = (const float*)d_in[15];
    const float* babs  = (const float*)d_in[16];
    const float* Wfor  = (const float*)d_in[17];
    const float* bfor  = (const float*)d_in[18];
    const float* lat0  = (const float*)d_in[19];
    float* out = (float*)d_out;

    cudaFuncSetAttribute(prepB_kernel,
                         cudaFuncAttributeMaxDynamicSharedMemorySize, SMEM_B);

    prepA_kernel<<<554, 128>>>(Wfuse, bfuse, Wabs, babs, Wfor, bfor,
                               EQd, EC, EIT, EUT, EHA);
    prepB_kernel<<<NBQ+2, 256, SMEM_B>>>(EQ, EC, q2c, q2cm, Wabs, Wfor);
    scan_kernel<<<B, SCAN_THREADS>>>(qseq, haseq, cseq, itseq, utseq,
                                     Wfor, lat0, out);
    post_kernel<<<(NOUT+POST_WPB-1)/POST_WPB, POST_THREADS>>>(qseq, q2c, q2cm, EC, out);
}